// round 3
// baseline (speedup 1.0000x reference)
#include <cuda_runtime.h>

#define KSEL   5000
#define NSEG   128
#define SEGCAP 16384
#define CAP    (NSEG * SEGCAP)
#define XGUESS 3.0f

// ---------------- scratch (static device globals; no allocation) ------------
__device__ unsigned int g_cand_u[CAP];
__device__ unsigned int g_cand_idx[CAP];
__device__ unsigned int g_scnt[NSEG];
__device__ unsigned int g_hist[2048];
__device__ unsigned int g_flag;   // 1 => fallback path active
__device__ unsigned int g_ulo;    // fallback bin threshold (monotone key)
__device__ unsigned int g_uT;     // exact threshold key
__device__ unsigned int g_gt;     // count strictly greater than threshold
__device__ unsigned int g_R;      // number of ties (== uT) to keep

// monotone float<->uint map: larger float => larger uint
__device__ __forceinline__ unsigned int f2u(float f) {
    unsigned int b = __float_as_uint(f);
    return (b & 0x80000000u) ? ~b : (b | 0x80000000u);
}
__device__ __forceinline__ float u2f(unsigned int u) {
    return __uint_as_float((u & 0x80000000u) ? (u & 0x7fffffffu) : ~u);
}

// ---------------- K0: init --------------------------------------------------
__global__ void k_init() {
    int t = blockIdx.x * blockDim.x + threadIdx.x;
    if (t < NSEG) g_scnt[t] = 0;
    if (t < 2048) g_hist[t] = 0;
    if (t == 0) { g_flag = 0; g_ulo = 0; g_uT = 0; g_gt = 0; g_R = 0; }
}

// ---------------- K1: streaming compaction with static guess ----------------
__global__ void k_compact_guess(const float* __restrict__ x, int n) {
    const int n4 = n >> 2;
    const float4* __restrict__ x4 = (const float4*)x;
    const unsigned seg = blockIdx.x & (NSEG - 1);
    const unsigned segbase = seg * SEGCAP;
    const int stride = gridDim.x * blockDim.x;

    for (int i = blockIdx.x * blockDim.x + threadIdx.x; i < n4; i += stride) {
        float4 v = x4[i];
        unsigned base = (unsigned)i << 2;
        if (v.x > XGUESS) { unsigned p = atomicAdd(&g_scnt[seg], 1u); if (p < SEGCAP) { g_cand_u[segbase + p] = f2u(v.x); g_cand_idx[segbase + p] = base + 0; } }
        if (v.y > XGUESS) { unsigned p = atomicAdd(&g_scnt[seg], 1u); if (p < SEGCAP) { g_cand_u[segbase + p] = f2u(v.y); g_cand_idx[segbase + p] = base + 1; } }
        if (v.z > XGUESS) { unsigned p = atomicAdd(&g_scnt[seg], 1u); if (p < SEGCAP) { g_cand_u[segbase + p] = f2u(v.z); g_cand_idx[segbase + p] = base + 2; } }
        if (v.w > XGUESS) { unsigned p = atomicAdd(&g_scnt[seg], 1u); if (p < SEGCAP) { g_cand_u[segbase + p] = f2u(v.w); g_cand_idx[segbase + p] = base + 3; } }
    }
    // scalar tail
    if (blockIdx.x == 0) {
        for (int i = (n4 << 2) + threadIdx.x; i < n; i += blockDim.x) {
            float v = x[i];
            if (v > XGUESS) { unsigned p = atomicAdd(&g_scnt[0], 1u); if (p < SEGCAP) { g_cand_u[p] = f2u(v); g_cand_idx[p] = (unsigned)i; } }
        }
    }
}

// ---------------- K2: validity check, set fallback flag ---------------------
__global__ void k_check() {   // 1 block, NSEG threads
    __shared__ unsigned sh[NSEG];
    __shared__ int s_ovf;
    if (threadIdx.x == 0) s_ovf = 0;
    __syncthreads();
    unsigned c = g_scnt[threadIdx.x];
    if (c > SEGCAP) s_ovf = 1;                 // benign race, all write 1
    sh[threadIdx.x] = (c > SEGCAP) ? (unsigned)SEGCAP : c;
    __syncthreads();
    for (int s = NSEG / 2; s > 0; s >>= 1) {
        if (threadIdx.x < (unsigned)s) sh[threadIdx.x] += sh[threadIdx.x + s];
        __syncthreads();
    }
    if (threadIdx.x == 0)
        g_flag = (sh[0] < (unsigned)KSEL || s_ovf) ? 1u : 0u;
}

// ---------------- K3a: fallback full histogram (early-exit normally) --------
__global__ void k_fb_hist(const float* __restrict__ x, int n) {
    if (g_flag == 0) return;
    __shared__ unsigned bins[2048];
    for (int t = threadIdx.x; t < 2048; t += blockDim.x) bins[t] = 0;
    __syncthreads();

    const int n4 = n >> 2;
    const float4* __restrict__ x4 = (const float4*)x;
    const int stride = gridDim.x * blockDim.x;
    for (int i = blockIdx.x * blockDim.x + threadIdx.x; i < n4; i += stride) {
        float4 v = x4[i];
        unsigned bb[4] = { f2u(v.x) >> 21, f2u(v.y) >> 21, f2u(v.z) >> 21, f2u(v.w) >> 21 };
        #pragma unroll
        for (int c = 0; c < 4; c++) {
            unsigned am = __activemask();
            unsigned peers = __match_any_sync(am, bb[c]);
            if ((threadIdx.x & 31u) == (unsigned)(__ffs(peers) - 1))
                atomicAdd(&bins[bb[c]], (unsigned)__popc(peers));
        }
    }
    if (blockIdx.x == 0) {
        for (int i = (n4 << 2) + threadIdx.x; i < n; i += blockDim.x)
            atomicAdd(&bins[f2u(x[i]) >> 21], 1u);
    }
    __syncthreads();
    for (int t = threadIdx.x; t < 2048; t += blockDim.x)
        if (bins[t]) atomicAdd(&g_hist[t], bins[t]);
}

// ---------------- K3b: fallback bin scan + segment reset --------------------
__global__ void k_fb_scan() {   // 1 block, 1024 threads
    if (g_flag == 0) return;
    __shared__ unsigned s[2048];
    __shared__ int sd;
    for (int t = threadIdx.x; t < 2048; t += blockDim.x) s[t] = g_hist[t];
    __syncthreads();
    for (int d = 1; d < 2048; d <<= 1) {               // suffix scan
        int t0 = threadIdx.x, t1 = threadIdx.x + 1024;
        unsigned a0 = (t0 + d < 2048) ? s[t0 + d] : 0;
        unsigned a1 = (t1 + d < 2048) ? s[t1 + d] : 0;
        __syncthreads();
        s[t0] += a0; s[t1] += a1;
        __syncthreads();
    }
    for (int t = threadIdx.x; t < 2048; t += blockDim.x) {
        unsigned nxt = (t + 1 < 2048) ? s[t + 1] : 0;
        if (s[t] >= (unsigned)KSEL && nxt < (unsigned)KSEL) sd = t;
    }
    __syncthreads();
    if (threadIdx.x < NSEG) g_scnt[threadIdx.x] = 0;
    if (threadIdx.x == 0) g_ulo = ((unsigned)sd) << 21;
}

// ---------------- K3c: fallback compaction ----------------------------------
__global__ void k_fb_compact(const float* __restrict__ x, int n) {
    if (g_flag == 0) return;
    const unsigned ulo = g_ulo;
    const int n4 = n >> 2;
    const float4* __restrict__ x4 = (const float4*)x;
    const unsigned seg = blockIdx.x & (NSEG - 1);
    const unsigned segbase = seg * SEGCAP;
    const int stride = gridDim.x * blockDim.x;

    for (int i = blockIdx.x * blockDim.x + threadIdx.x; i < n4; i += stride) {
        float4 v = x4[i];
        unsigned base = (unsigned)i << 2;
        unsigned u;
        u = f2u(v.x); if (u >= ulo) { unsigned p = atomicAdd(&g_scnt[seg], 1u); if (p < SEGCAP) { g_cand_u[segbase + p] = u; g_cand_idx[segbase + p] = base + 0; } }
        u = f2u(v.y); if (u >= ulo) { unsigned p = atomicAdd(&g_scnt[seg], 1u); if (p < SEGCAP) { g_cand_u[segbase + p] = u; g_cand_idx[segbase + p] = base + 1; } }
        u = f2u(v.z); if (u >= ulo) { unsigned p = atomicAdd(&g_scnt[seg], 1u); if (p < SEGCAP) { g_cand_u[segbase + p] = u; g_cand_idx[segbase + p] = base + 2; } }
        u = f2u(v.w); if (u >= ulo) { unsigned p = atomicAdd(&g_scnt[seg], 1u); if (p < SEGCAP) { g_cand_u[segbase + p] = u; g_cand_idx[segbase + p] = base + 3; } }
    }
    if (blockIdx.x == 0) {
        for (int i = (n4 << 2) + threadIdx.x; i < n; i += blockDim.x) {
            unsigned u = f2u(x[i]);
            if (u >= ulo) { unsigned p = atomicAdd(&g_scnt[0], 1u); if (p < SEGCAP) { g_cand_u[p] = u; g_cand_idx[p] = (unsigned)i; } }
        }
    }
}

// ---------------- K4: exact radix select over candidates --------------------
__global__ void k_select() {   // 1 block, 1024 threads
    __shared__ unsigned bins[2048];
    __shared__ unsigned sh_d;
    unsigned prefix = 0, prefmask = 0, need = KSEL, gt = 0;
    const int shifts[3] = { 21, 10, 0 };
    const int widths[3] = { 11, 11, 10 };

    for (int r = 0; r < 3; r++) {
        const int sh = shifts[r];
        const int nb = 1 << widths[r];
        for (int t = threadIdx.x; t < nb; t += blockDim.x) bins[t] = 0;
        __syncthreads();

        for (int s = 0; s < NSEG; s++) {
            unsigned cnt = g_scnt[s]; if (cnt > SEGCAP) cnt = SEGCAP;
            const unsigned* __restrict__ cu = g_cand_u + s * SEGCAP;
            for (unsigned base = 0; base < cnt; base += blockDim.x) {
                unsigned j = base + threadIdx.x;
                bool valid = (j < cnt);
                unsigned u = valid ? cu[j] : 0u;
                bool act = valid && ((u & prefmask) == prefix);
                unsigned b = (u >> sh) & (unsigned)(nb - 1);
                unsigned m = __ballot_sync(0xffffffffu, act);
                if (act) {
                    unsigned peers = __match_any_sync(m, b);
                    if ((threadIdx.x & 31u) == (unsigned)(__ffs(peers) - 1))
                        atomicAdd(&bins[b], (unsigned)__popc(peers));
                }
            }
        }
        __syncthreads();

        // suffix scan of bins[0..nb)
        for (int d = 1; d < nb; d <<= 1) {
            unsigned tmp[2]; int c = 0;
            for (int t = threadIdx.x; t < nb; t += blockDim.x)
                tmp[c++] = (t + d < nb) ? bins[t + d] : 0;
            __syncthreads();
            c = 0;
            for (int t = threadIdx.x; t < nb; t += blockDim.x)
                bins[t] += tmp[c++];
            __syncthreads();
        }
        for (int t = threadIdx.x; t < nb; t += blockDim.x) {
            unsigned nxt = (t + 1 < nb) ? bins[t + 1] : 0;
            if (bins[t] >= need && nxt < need) sh_d = (unsigned)t;
        }
        __syncthreads();
        unsigned d = sh_d;
        unsigned above = (d + 1 < (unsigned)nb) ? bins[d + 1] : 0;
        __syncthreads();   // all reads done before next round zeroes bins

        gt += above;
        need -= above;
        prefix |= d << sh;
        prefmask |= ((unsigned)(nb - 1)) << sh;
    }
    if (threadIdx.x == 0) { g_uT = prefix; g_gt = gt; g_R = need; }
}

// ---------------- K5: gather + tie-break + bitonic sort by index ------------
#define SORT_N 8192
#define EQ_N   2048
#define FIN_SMEM (SORT_N * 8 + EQ_N * 4)

__global__ void k_finalize(float* __restrict__ out) {   // 1 block, 1024 threads
    extern __shared__ unsigned long long sm[];
    unsigned long long* arr = sm;               // SORT_N entries
    unsigned* eq = (unsigned*)(sm + SORT_N);    // EQ_N entries
    __shared__ unsigned s_ngt, s_neq;

    if (threadIdx.x == 0) { s_ngt = 0; s_neq = 0; }
    __syncthreads();
    const unsigned uT = g_uT;

    for (int s = 0; s < NSEG; s++) {
        unsigned cnt = g_scnt[s]; if (cnt > SEGCAP) cnt = SEGCAP;
        const unsigned* __restrict__ cu = g_cand_u + s * SEGCAP;
        const unsigned* __restrict__ ci = g_cand_idx + s * SEGCAP;
        for (unsigned j = threadIdx.x; j < cnt; j += blockDim.x) {
            unsigned u = cu[j];
            if (u > uT) {
                unsigned p = atomicAdd(&s_ngt, 1u);
                if (p < SORT_N) arr[p] = ((unsigned long long)ci[j] << 32) | (unsigned long long)u;
            } else if (u == uT) {
                unsigned p = atomicAdd(&s_neq, 1u);
                if (p < EQ_N) eq[p] = ci[j];
            }
        }
    }
    __syncthreads();

    unsigned ngt = s_ngt; if (ngt > SORT_N) ngt = SORT_N;
    unsigned neq = s_neq; if (neq > EQ_N) neq = EQ_N;
    unsigned R = g_R; if (R > neq) R = neq;

    if (neq > R) {   // need R smallest indices among ties: sort eq ascending
        for (unsigned t = threadIdx.x; t < EQ_N; t += blockDim.x)
            if (t >= neq) eq[t] = 0xffffffffu;
        __syncthreads();
        for (unsigned k = 2; k <= EQ_N; k <<= 1) {
            for (unsigned j = k >> 1; j > 0; j >>= 1) {
                for (unsigned t = threadIdx.x; t < EQ_N / 2; t += blockDim.x) {
                    unsigned i = ((t & ~(j - 1)) << 1) | (t & (j - 1));
                    unsigned p = i | j;
                    unsigned a = eq[i], b = eq[p];
                    bool up = ((i & k) == 0);
                    if ((a > b) == up) { eq[i] = b; eq[p] = a; }
                }
                __syncthreads();
            }
        }
    }
    __syncthreads();

    // append R tie entries, pad, sort everything by (index<<32|key) ascending
    for (unsigned t = threadIdx.x; t < R; t += blockDim.x)
        arr[ngt + t] = ((unsigned long long)eq[t] << 32) | (unsigned long long)uT;
    unsigned total = ngt + R;
    for (unsigned t = threadIdx.x; t < SORT_N; t += blockDim.x)
        if (t >= total) arr[t] = 0xffffffffffffffffULL;
    __syncthreads();

    for (unsigned k = 2; k <= SORT_N; k <<= 1) {
        for (unsigned j = k >> 1; j > 0; j >>= 1) {
            for (unsigned t = threadIdx.x; t < SORT_N / 2; t += blockDim.x) {
                unsigned i = ((t & ~(j - 1)) << 1) | (t & (j - 1));
                unsigned p = i | j;
                unsigned long long a = arr[i], b = arr[p];
                bool up = ((i & k) == 0);
                if ((a > b) == up) { arr[i] = b; arr[p] = a; }
            }
            __syncthreads();
        }
    }

    for (unsigned t = threadIdx.x; t < KSEL; t += blockDim.x)
        out[t] = u2f((unsigned)(arr[t] & 0xffffffffu));
}

// ---------------- launch ----------------------------------------------------
extern "C" void kernel_launch(void* const* d_in, const int* in_sizes, int n_in,
                              void* d_out, int out_size) {
    const float* x = (const float*)d_in[0];
    int n = in_sizes[0];
    float* out = (float*)d_out;

    static bool attr_done = false;
    // idempotent; safe to repeat, but setting every call is also fine
    cudaFuncSetAttribute(k_finalize, cudaFuncAttributeMaxDynamicSharedMemorySize, FIN_SMEM);
    (void)attr_done;

    k_init<<<2, 1024>>>();
    k_compact_guess<<<2048, 256>>>(x, n);
    k_check<<<1, NSEG>>>();
    k_fb_hist<<<1024, 256>>>(x, n);
    k_fb_scan<<<1, 1024>>>();
    k_fb_compact<<<1024, 256>>>(x, n);
    k_select<<<1, 1024>>>();
    k_finalize<<<1, 1024, FIN_SMEM>>>(out);
}

// round 4
// speedup vs baseline: 2.5893x; 2.5893x over previous
#include <cuda_runtime.h>

#define KSEL   5000
#define NSEG   128
#define SEGCAP 8192
#define CAP    (NSEG * SEGCAP)
#define XGUESS 3.55f

// ---------------- scratch (static device globals; no allocation) ------------
__device__ unsigned int g_cand_u[CAP];
__device__ unsigned int g_cand_idx[CAP];
__device__ unsigned int g_du[CAP];      // dense candidate keys
__device__ unsigned int g_didx[CAP];    // dense candidate indices
__device__ unsigned int g_scnt[NSEG];
__device__ unsigned int g_segoff[NSEG];
__device__ unsigned int g_total;
__device__ unsigned int g_hist[2048];
__device__ unsigned int g_flag;   // 1 => fallback path active
__device__ unsigned int g_ulo;    // fallback bin threshold (monotone key)

// monotone float<->uint map: larger float => larger uint
__device__ __forceinline__ unsigned int f2u(float f) {
    unsigned int b = __float_as_uint(f);
    return (b & 0x80000000u) ? ~b : (b | 0x80000000u);
}
__device__ __forceinline__ float u2f(unsigned int u) {
    return __uint_as_float((u & 0x80000000u) ? (u & 0x7fffffffu) : ~u);
}

// ---------------- K0: init --------------------------------------------------
__global__ void k_init() {
    int t = blockIdx.x * blockDim.x + threadIdx.x;
    if (t < NSEG) g_scnt[t] = 0;
    if (t < 2048) g_hist[t] = 0;
    if (t == 0) { g_flag = 0; g_ulo = 0; g_total = 0; }
}

// ---------------- K1: streaming compaction with static guess ----------------
__global__ void k_compact_guess(const float* __restrict__ x, int n) {
    const int n4 = n >> 2;
    const float4* __restrict__ x4 = (const float4*)x;
    const unsigned seg = blockIdx.x & (NSEG - 1);
    const unsigned segbase = seg * SEGCAP;
    const int stride = gridDim.x * blockDim.x;

    for (int i = blockIdx.x * blockDim.x + threadIdx.x; i < n4; i += stride) {
        float4 v = x4[i];
        unsigned base = (unsigned)i << 2;
        if (v.x > XGUESS) { unsigned p = atomicAdd(&g_scnt[seg], 1u); if (p < SEGCAP) { g_cand_u[segbase + p] = f2u(v.x); g_cand_idx[segbase + p] = base + 0; } }
        if (v.y > XGUESS) { unsigned p = atomicAdd(&g_scnt[seg], 1u); if (p < SEGCAP) { g_cand_u[segbase + p] = f2u(v.y); g_cand_idx[segbase + p] = base + 1; } }
        if (v.z > XGUESS) { unsigned p = atomicAdd(&g_scnt[seg], 1u); if (p < SEGCAP) { g_cand_u[segbase + p] = f2u(v.z); g_cand_idx[segbase + p] = base + 2; } }
        if (v.w > XGUESS) { unsigned p = atomicAdd(&g_scnt[seg], 1u); if (p < SEGCAP) { g_cand_u[segbase + p] = f2u(v.w); g_cand_idx[segbase + p] = base + 3; } }
    }
    // scalar tail
    if (blockIdx.x == 0) {
        for (int i = (n4 << 2) + threadIdx.x; i < n; i += blockDim.x) {
            float v = x[i];
            if (v > XGUESS) { unsigned p = atomicAdd(&g_scnt[0], 1u); if (p < SEGCAP) { g_cand_u[p] = f2u(v); g_cand_idx[p] = (unsigned)i; } }
        }
    }
}

// ---------------- K2: validity check, set fallback flag ---------------------
__global__ void k_check() {   // 1 block, NSEG threads
    __shared__ unsigned sh[NSEG];
    __shared__ int s_ovf;
    if (threadIdx.x == 0) s_ovf = 0;
    __syncthreads();
    unsigned c = g_scnt[threadIdx.x];
    if (c > SEGCAP) s_ovf = 1;                 // benign race, all write 1
    sh[threadIdx.x] = (c > SEGCAP) ? (unsigned)SEGCAP : c;
    __syncthreads();
    for (int s = NSEG / 2; s > 0; s >>= 1) {
        if (threadIdx.x < (unsigned)s) sh[threadIdx.x] += sh[threadIdx.x + s];
        __syncthreads();
    }
    if (threadIdx.x == 0)
        g_flag = (sh[0] < (unsigned)KSEL || s_ovf) ? 1u : 0u;
}

// ---------------- K3a: fallback full histogram (early-exit normally) --------
__global__ void k_fb_hist(const float* __restrict__ x, int n) {
    if (g_flag == 0) return;
    __shared__ unsigned bins[2048];
    for (int t = threadIdx.x; t < 2048; t += blockDim.x) bins[t] = 0;
    __syncthreads();

    const int n4 = n >> 2;
    const float4* __restrict__ x4 = (const float4*)x;
    const int stride = gridDim.x * blockDim.x;
    for (int i = blockIdx.x * blockDim.x + threadIdx.x; i < n4; i += stride) {
        float4 v = x4[i];
        unsigned bb[4] = { f2u(v.x) >> 21, f2u(v.y) >> 21, f2u(v.z) >> 21, f2u(v.w) >> 21 };
        #pragma unroll
        for (int c = 0; c < 4; c++) {
            unsigned am = __activemask();
            unsigned peers = __match_any_sync(am, bb[c]);
            if ((threadIdx.x & 31u) == (unsigned)(__ffs(peers) - 1))
                atomicAdd(&bins[bb[c]], (unsigned)__popc(peers));
        }
    }
    if (blockIdx.x == 0) {
        for (int i = (n4 << 2) + threadIdx.x; i < n; i += blockDim.x)
            atomicAdd(&bins[f2u(x[i]) >> 21], 1u);
    }
    __syncthreads();
    for (int t = threadIdx.x; t < 2048; t += blockDim.x)
        if (bins[t]) atomicAdd(&g_hist[t], bins[t]);
}

// ---------------- K3b: fallback bin scan + segment reset --------------------
__global__ void k_fb_scan() {   // 1 block, 1024 threads
    if (g_flag == 0) return;
    __shared__ unsigned s[2048];
    __shared__ int sd;
    for (int t = threadIdx.x; t < 2048; t += blockDim.x) s[t] = g_hist[t];
    __syncthreads();
    for (int d = 1; d < 2048; d <<= 1) {               // suffix scan
        int t0 = threadIdx.x, t1 = threadIdx.x + 1024;
        unsigned a0 = (t0 + d < 2048) ? s[t0 + d] : 0;
        unsigned a1 = (t1 + d < 2048) ? s[t1 + d] : 0;
        __syncthreads();
        s[t0] += a0; s[t1] += a1;
        __syncthreads();
    }
    for (int t = threadIdx.x; t < 2048; t += blockDim.x) {
        unsigned nxt = (t + 1 < 2048) ? s[t + 1] : 0;
        if (s[t] >= (unsigned)KSEL && nxt < (unsigned)KSEL) sd = t;
    }
    __syncthreads();
    if (threadIdx.x < NSEG) g_scnt[threadIdx.x] = 0;
    if (threadIdx.x == 0) g_ulo = ((unsigned)sd) << 21;
}

// ---------------- K3c: fallback compaction ----------------------------------
__global__ void k_fb_compact(const float* __restrict__ x, int n) {
    if (g_flag == 0) return;
    const unsigned ulo = g_ulo;
    const int n4 = n >> 2;
    const float4* __restrict__ x4 = (const float4*)x;
    const unsigned seg = blockIdx.x & (NSEG - 1);
    const unsigned segbase = seg * SEGCAP;
    const int stride = gridDim.x * blockDim.x;

    for (int i = blockIdx.x * blockDim.x + threadIdx.x; i < n4; i += stride) {
        float4 v = x4[i];
        unsigned base = (unsigned)i << 2;
        unsigned u;
        u = f2u(v.x); if (u >= ulo) { unsigned p = atomicAdd(&g_scnt[seg], 1u); if (p < SEGCAP) { g_cand_u[segbase + p] = u; g_cand_idx[segbase + p] = base + 0; } }
        u = f2u(v.y); if (u >= ulo) { unsigned p = atomicAdd(&g_scnt[seg], 1u); if (p < SEGCAP) { g_cand_u[segbase + p] = u; g_cand_idx[segbase + p] = base + 1; } }
        u = f2u(v.z); if (u >= ulo) { unsigned p = atomicAdd(&g_scnt[seg], 1u); if (p < SEGCAP) { g_cand_u[segbase + p] = u; g_cand_idx[segbase + p] = base + 2; } }
        u = f2u(v.w); if (u >= ulo) { unsigned p = atomicAdd(&g_scnt[seg], 1u); if (p < SEGCAP) { g_cand_u[segbase + p] = u; g_cand_idx[segbase + p] = base + 3; } }
    }
    if (blockIdx.x == 0) {
        for (int i = (n4 << 2) + threadIdx.x; i < n; i += blockDim.x) {
            unsigned u = f2u(x[i]);
            if (u >= ulo) { unsigned p = atomicAdd(&g_scnt[0], 1u); if (p < SEGCAP) { g_cand_u[p] = u; g_cand_idx[p] = (unsigned)i; } }
        }
    }
}

// ---------------- K4: segment offsets (works for guess AND fallback path) ---
__global__ void k_offsets() {   // 1 block, NSEG threads
    __shared__ unsigned sh[NSEG];
    unsigned c = g_scnt[threadIdx.x];
    if (c > SEGCAP) c = SEGCAP;
    sh[threadIdx.x] = c;
    __syncthreads();
    // Hillis-Steele inclusive scan
    for (int d = 1; d < NSEG; d <<= 1) {
        unsigned v = (threadIdx.x >= (unsigned)d) ? sh[threadIdx.x - d] : 0u;
        __syncthreads();
        sh[threadIdx.x] += v;
        __syncthreads();
    }
    g_segoff[threadIdx.x] = sh[threadIdx.x] - ((g_scnt[threadIdx.x] > SEGCAP) ? SEGCAP : g_scnt[threadIdx.x]);
    if (threadIdx.x == NSEG - 1) g_total = sh[NSEG - 1];
}

// ---------------- K5: densify candidates ------------------------------------
__global__ void k_densify() {   // NSEG blocks
    const unsigned s = blockIdx.x;
    unsigned cnt = g_scnt[s]; if (cnt > SEGCAP) cnt = SEGCAP;
    const unsigned off = g_segoff[s];
    const unsigned* __restrict__ cu = g_cand_u + s * SEGCAP;
    const unsigned* __restrict__ ci = g_cand_idx + s * SEGCAP;
    for (unsigned j = threadIdx.x; j < cnt; j += blockDim.x) {
        g_du[off + j] = cu[j];
        g_didx[off + j] = ci[j];
    }
}

// ---------------- K6: fused exact select + gather + sort + output -----------
#define SORT_N 8192
#define EQ_N   2048
#define FIN_SMEM (SORT_N * 8 + 2048 * 4 + EQ_N * 4)

__global__ void k_final(float* __restrict__ out) {   // 1 block, 1024 threads
    extern __shared__ unsigned long long sm[];
    unsigned long long* arr = sm;                     // SORT_N u64
    unsigned* bins = (unsigned*)(sm + SORT_N);        // 2048 u32
    unsigned* eq = bins + 2048;                       // EQ_N u32
    __shared__ unsigned sh_d, s_ngt, s_neq;

    unsigned T = g_total; if (T > CAP) T = CAP;

    // ---- exact radix select over dense candidates (3 rounds: 11/11/10 bits)
    unsigned prefix = 0, prefmask = 0, need = KSEL;
    const int shifts[3] = { 21, 10, 0 };
    const int widths[3] = { 11, 11, 10 };

    for (int r = 0; r < 3; r++) {
        const int sh = shifts[r];
        const int nb = 1 << widths[r];
        for (int t = threadIdx.x; t < nb; t += blockDim.x) bins[t] = 0;
        __syncthreads();

        for (unsigned base = 0; base < T; base += blockDim.x) {
            unsigned j = base + threadIdx.x;
            bool valid = (j < T);
            unsigned u = valid ? g_du[j] : 0u;
            bool act = valid && ((u & prefmask) == prefix);
            unsigned b = (u >> sh) & (unsigned)(nb - 1);
            unsigned m = __ballot_sync(0xffffffffu, act);
            if (act) {
                unsigned peers = __match_any_sync(m, b);
                if ((threadIdx.x & 31u) == (unsigned)(__ffs(peers) - 1))
                    atomicAdd(&bins[b], (unsigned)__popc(peers));
            }
        }
        __syncthreads();

        // suffix scan of bins[0..nb)
        for (int d = 1; d < nb; d <<= 1) {
            unsigned tmp[2]; int c = 0;
            for (int t = threadIdx.x; t < nb; t += blockDim.x)
                tmp[c++] = (t + d < nb) ? bins[t + d] : 0;
            __syncthreads();
            c = 0;
            for (int t = threadIdx.x; t < nb; t += blockDim.x)
                bins[t] += tmp[c++];
            __syncthreads();
        }
        for (int t = threadIdx.x; t < nb; t += blockDim.x) {
            unsigned nxt = (t + 1 < nb) ? bins[t + 1] : 0;
            if (bins[t] >= need && nxt < need) sh_d = (unsigned)t;
        }
        __syncthreads();
        unsigned d = sh_d;
        unsigned above = (d + 1 < (unsigned)nb) ? bins[d + 1] : 0;
        __syncthreads();   // all reads done before next round zeroes bins

        need -= above;
        prefix |= d << sh;
        prefmask |= ((unsigned)(nb - 1)) << sh;
    }
    const unsigned uT = prefix;
    const unsigned R0 = need;   // ties to keep (smallest indices first)

    // ---- gather winners + ties
    if (threadIdx.x == 0) { s_ngt = 0; s_neq = 0; }
    __syncthreads();
    for (unsigned j = threadIdx.x; j < T; j += blockDim.x) {
        unsigned u = g_du[j];
        if (u > uT) {
            unsigned p = atomicAdd(&s_ngt, 1u);
            if (p < SORT_N) arr[p] = ((unsigned long long)g_didx[j] << 32) | (unsigned long long)u;
        } else if (u == uT) {
            unsigned p = atomicAdd(&s_neq, 1u);
            if (p < EQ_N) eq[p] = g_didx[j];
        }
    }
    __syncthreads();

    unsigned ngt = s_ngt; if (ngt > SORT_N) ngt = SORT_N;
    unsigned neq = s_neq; if (neq > EQ_N) neq = EQ_N;
    unsigned R = R0; if (R > neq) R = neq;

    if (neq > R) {   // sort tie indices ascending, keep R smallest
        for (unsigned t = threadIdx.x; t < EQ_N; t += blockDim.x)
            if (t >= neq) eq[t] = 0xffffffffu;
        __syncthreads();
        for (unsigned k = 2; k <= EQ_N; k <<= 1) {
            for (unsigned j = k >> 1; j > 0; j >>= 1) {
                for (unsigned t = threadIdx.x; t < EQ_N / 2; t += blockDim.x) {
                    unsigned i = ((t & ~(j - 1)) << 1) | (t & (j - 1));
                    unsigned p = i | j;
                    unsigned a = eq[i], b = eq[p];
                    bool up = ((i & k) == 0);
                    if ((a > b) == up) { eq[i] = b; eq[p] = a; }
                }
                __syncthreads();
            }
        }
    }
    __syncthreads();

    // ---- append R ties, pad, bitonic sort ascending by (idx<<32|key)
    for (unsigned t = threadIdx.x; t < R; t += blockDim.x)
        arr[ngt + t] = ((unsigned long long)eq[t] << 32) | (unsigned long long)uT;
    unsigned total = ngt + R;
    for (unsigned t = threadIdx.x; t < SORT_N; t += blockDim.x)
        if (t >= total) arr[t] = 0xffffffffffffffffULL;
    __syncthreads();

    for (unsigned k = 2; k <= SORT_N; k <<= 1) {
        for (unsigned j = k >> 1; j > 0; j >>= 1) {
            for (unsigned t = threadIdx.x; t < SORT_N / 2; t += blockDim.x) {
                unsigned i = ((t & ~(j - 1)) << 1) | (t & (j - 1));
                unsigned p = i | j;
                unsigned long long a = arr[i], b = arr[p];
                bool up = ((i & k) == 0);
                if ((a > b) == up) { arr[i] = b; arr[p] = a; }
            }
            __syncthreads();
        }
    }

    for (unsigned t = threadIdx.x; t < KSEL; t += blockDim.x)
        out[t] = u2f((unsigned)(arr[t] & 0xffffffffu));
}

// ---------------- launch ----------------------------------------------------
extern "C" void kernel_launch(void* const* d_in, const int* in_sizes, int n_in,
                              void* d_out, int out_size) {
    const float* x = (const float*)d_in[0];
    int n = in_sizes[0];
    float* out = (float*)d_out;

    cudaFuncSetAttribute(k_final, cudaFuncAttributeMaxDynamicSharedMemorySize, FIN_SMEM);

    k_init<<<2, 1024>>>();
    k_compact_guess<<<2048, 256>>>(x, n);
    k_check<<<1, NSEG>>>();
    k_fb_hist<<<1024, 256>>>(x, n);
    k_fb_scan<<<1, 1024>>>();
    k_fb_compact<<<1024, 256>>>(x, n);
    k_offsets<<<1, NSEG>>>();
    k_densify<<<NSEG, 256>>>();
    k_final<<<1, 1024, FIN_SMEM>>>(out);
}

// round 5
// speedup vs baseline: 4.5946x; 1.7745x over previous
#include <cuda_runtime.h>

#define KSEL   5000
#define CAP    65536
#define XGUESS 3.55f

// ---------------- scratch (static device globals; zero-initialized) ---------
__device__ unsigned int g_du[CAP];     // dense candidate keys (monotone u32)
__device__ unsigned int g_didx[CAP];   // dense candidate original indices
__device__ unsigned int g_total;       // dense candidate count (reset by k_final)

// monotone float<->uint map: larger float => larger uint
__device__ __forceinline__ unsigned int f2u(float f) {
    unsigned int b = __float_as_uint(f);
    return (b & 0x80000000u) ? ~b : (b | 0x80000000u);
}
__device__ __forceinline__ float u2f(unsigned int u) {
    return __uint_as_float((u & 0x80000000u) ? (u & 0x7fffffffu) : ~u);
}

__device__ __forceinline__ void emit(float v, unsigned idx) {
    unsigned p = atomicAdd(&g_total, 1u);
    if (p < CAP) { g_du[p] = f2u(v); g_didx[p] = idx; }
}

// ---------------- K1: streaming compaction (dense, warp-gated) --------------
__device__ __forceinline__ void proc4(float4 v, unsigned base) {
    float mx = fmaxf(fmaxf(v.x, v.y), fmaxf(v.z, v.w));
    unsigned am = __activemask();
    if (__ballot_sync(am, mx > XGUESS)) {
        if (v.x > XGUESS) emit(v.x, base + 0);
        if (v.y > XGUESS) emit(v.y, base + 1);
        if (v.z > XGUESS) emit(v.z, base + 2);
        if (v.w > XGUESS) emit(v.w, base + 3);
    }
}

__global__ void __launch_bounds__(256) k_compact(const float* __restrict__ x, int n) {
    const int n4 = n >> 2;
    const float4* __restrict__ x4 = (const float4*)x;
    const int stride = gridDim.x * blockDim.x;
    int i = blockIdx.x * blockDim.x + threadIdx.x;

    for (; i + 3 * stride < n4; i += 4 * stride) {
        float4 a = x4[i];
        float4 b = x4[i + stride];
        float4 c = x4[i + 2 * stride];
        float4 d = x4[i + 3 * stride];
        proc4(a, (unsigned)i << 2);
        proc4(b, (unsigned)(i + stride) << 2);
        proc4(c, (unsigned)(i + 2 * stride) << 2);
        proc4(d, (unsigned)(i + 3 * stride) << 2);
    }
    for (; i < n4; i += stride)
        proc4(x4[i], (unsigned)i << 2);

    // scalar tail (n not divisible by 4)
    if (blockIdx.x == 0) {
        for (int t = (n4 << 2) + threadIdx.x; t < n; t += blockDim.x) {
            float v = x[t];
            if (v > XGUESS) emit(v, (unsigned)t);
        }
    }
}

// ---------------- K2: exact single-block fallback (never runs normally) -----
__global__ void __launch_bounds__(1024) k_fallback(const float* __restrict__ x, int n) {
    {
        unsigned tot = g_total;
        if (tot >= (unsigned)KSEL && tot <= (unsigned)CAP) return;  // fast exit
    }
    __shared__ unsigned bins[2048];
    __shared__ unsigned sh_d;
    const unsigned tid = threadIdx.x;

    // ---- exact value threshold: 3-level radix (11/11/10 bits), descending
    unsigned prefix = 0, prefmask = 0, need = KSEL;
    const int vsh[3] = { 21, 10, 0 };
    const int vwd[3] = { 11, 11, 10 };
    for (int r = 0; r < 3; r++) {
        const int sh = vsh[r];
        const int nb = 1 << vwd[r];
        for (int t = tid; t < nb; t += 1024) bins[t] = 0;
        __syncthreads();
        for (int i = tid; i < n; i += 1024) {
            unsigned u = f2u(x[i]);
            if ((u & prefmask) == prefix) {
                unsigned b = (u >> sh) & (unsigned)(nb - 1);
                unsigned am = __activemask();
                unsigned peers = __match_any_sync(am, b);
                if ((tid & 31u) == (unsigned)(__ffs(peers) - 1))
                    atomicAdd(&bins[b], (unsigned)__popc(peers));
            }
        }
        __syncthreads();
        // suffix scan
        for (int d = 1; d < nb; d <<= 1) {
            unsigned t0 = tid, t1 = tid + 1024;
            unsigned a0 = (t0 < (unsigned)nb && t0 + d < (unsigned)nb) ? bins[t0 + d] : 0;
            unsigned a1 = (t1 < (unsigned)nb && t1 + d < (unsigned)nb) ? bins[t1 + d] : 0;
            __syncthreads();
            if (t0 < (unsigned)nb) bins[t0] += a0;
            if (t1 < (unsigned)nb) bins[t1] += a1;
            __syncthreads();
        }
        for (int t = tid; t < nb; t += 1024) {
            unsigned nxt = (t + 1 < nb) ? bins[t + 1] : 0;
            if (bins[t] >= need && nxt < need) sh_d = (unsigned)t;
        }
        __syncthreads();
        unsigned d = sh_d;
        unsigned above = (d + 1 < (unsigned)nb) ? bins[d + 1] : 0;
        __syncthreads();
        need -= above;
        prefix |= d << sh;
        prefmask |= ((unsigned)(nb - 1)) << sh;
    }
    const unsigned uT = prefix;
    const unsigned R = need;          // ties to keep, smallest indices first

    // ---- exact tie-index threshold: 3-level radix (11/11/4 bits), ascending
    unsigned iprefix = 0, imask = 0, needi = R;
    const int ish[3] = { 15, 4, 0 };
    const int iwd[3] = { 11, 11, 4 };
    if (R > 0) {
        for (int r = 0; r < 3; r++) {
            const int sh = ish[r];
            const int nb = 1 << iwd[r];
            for (int t = tid; t < nb; t += 1024) bins[t] = 0;
            __syncthreads();
            for (int i = tid; i < n; i += 1024) {
                unsigned u = f2u(x[i]);
                if (u == uT && (((unsigned)i & imask) == iprefix))
                    atomicAdd(&bins[((unsigned)i >> sh) & (unsigned)(nb - 1)], 1u);
            }
            __syncthreads();
            // forward (ascending) inclusive scan
            for (int d = 1; d < nb; d <<= 1) {
                unsigned t0 = tid, t1 = tid + 1024;
                unsigned a0 = (t0 < (unsigned)nb && t0 >= (unsigned)d) ? bins[t0 - d] : 0;
                unsigned a1 = (t1 < (unsigned)nb && t1 >= (unsigned)d) ? bins[t1 - d] : 0;
                __syncthreads();
                if (t0 < (unsigned)nb) bins[t0] += a0;
                if (t1 < (unsigned)nb) bins[t1] += a1;
                __syncthreads();
            }
            for (int t = tid; t < nb; t += 1024) {
                unsigned prev = (t > 0) ? bins[t - 1] : 0;
                if (bins[t] >= needi && prev < needi) sh_d = (unsigned)t;
            }
            __syncthreads();
            unsigned d = sh_d;
            unsigned below = (d > 0) ? bins[d - 1] : 0;
            __syncthreads();
            needi -= below;
            iprefix |= d << sh;
            imask |= ((unsigned)(nb - 1)) << sh;
        }
    }
    // iprefix is the exact R-th smallest tie index (indices are unique)

    // ---- compact exactly KSEL winners
    if (tid == 0) g_total = 0;
    __syncthreads();
    for (int i = tid; i < n; i += 1024) {
        unsigned u = f2u(x[i]);
        bool keep = (u > uT) || (R > 0 && u == uT && (unsigned)i <= iprefix);
        if (keep) {
            unsigned p = atomicAdd(&g_total, 1u);
            if (p < CAP) { g_du[p] = u; g_didx[p] = (unsigned)i; }
        }
    }
}

// ---------------- K3: fused select + gather + bucket sort + output ----------
#define SRC_N  8192
#define NB     8192
#define EQ_N   2048
#define FIN_SMEM (SRC_N*8 + SRC_N*8 + NB*4 + EQ_N*4)

__global__ void __launch_bounds__(1024) k_final(float* __restrict__ out) {
    extern __shared__ unsigned long long sm[];
    unsigned long long* src = sm;                   // SRC_N u64
    unsigned long long* dst = src + SRC_N;          // SRC_N u64
    unsigned* bcnt = (unsigned*)(dst + SRC_N);      // NB u32 (also select bins)
    unsigned* eq = bcnt + NB;                       // EQ_N u32
    __shared__ unsigned sh_d, s_ngt, s_neq, wsum[32];
    const unsigned tid = threadIdx.x;

    unsigned T = g_total; if (T > CAP) T = CAP;

    // ---- exact radix select over candidates (3 rounds: 11/11/10 bits)
    unsigned prefix = 0, prefmask = 0, need = KSEL;
    const int shifts[3] = { 21, 10, 0 };
    const int widths[3] = { 11, 11, 10 };
    unsigned* bins = bcnt;

    for (int r = 0; r < 3; r++) {
        const int sh = shifts[r];
        const int nb = 1 << widths[r];
        for (int t = tid; t < nb; t += 1024) bins[t] = 0;
        __syncthreads();

        for (unsigned base = 0; base < T; base += 1024) {
            unsigned j = base + tid;
            bool valid = (j < T);
            unsigned u = valid ? g_du[j] : 0u;
            bool act = valid && ((u & prefmask) == prefix);
            unsigned b = (u >> sh) & (unsigned)(nb - 1);
            unsigned m = __ballot_sync(0xffffffffu, act);
            if (act) {
                unsigned peers = __match_any_sync(m, b);
                if ((tid & 31u) == (unsigned)(__ffs(peers) - 1))
                    atomicAdd(&bins[b], (unsigned)__popc(peers));
            }
        }
        __syncthreads();

        // suffix scan
        for (int d = 1; d < nb; d <<= 1) {
            unsigned tmp[2]; int c = 0;
            for (int t = tid; t < nb; t += 1024)
                tmp[c++] = (t + d < nb) ? bins[t + d] : 0;
            __syncthreads();
            c = 0;
            for (int t = tid; t < nb; t += 1024)
                bins[t] += tmp[c++];
            __syncthreads();
        }
        for (int t = tid; t < nb; t += 1024) {
            unsigned nxt = (t + 1 < nb) ? bins[t + 1] : 0;
            if (bins[t] >= need && nxt < need) sh_d = (unsigned)t;
        }
        __syncthreads();
        unsigned d = sh_d;
        unsigned above = (d + 1 < (unsigned)nb) ? bins[d + 1] : 0;
        __syncthreads();
        need -= above;
        prefix |= d << sh;
        prefmask |= ((unsigned)(nb - 1)) << sh;
    }
    const unsigned uT = prefix;
    const unsigned R0 = need;

    // ---- gather winners (> uT) and tie indices (== uT)
    if (tid == 0) { s_ngt = 0; s_neq = 0; }
    __syncthreads();
    for (unsigned j = tid; j < T; j += 1024) {
        unsigned u = g_du[j];
        if (u > uT) {
            unsigned p = atomicAdd(&s_ngt, 1u);
            if (p < SRC_N) src[p] = ((unsigned long long)g_didx[j] << 32) | (unsigned long long)u;
        } else if (u == uT) {
            unsigned p = atomicAdd(&s_neq, 1u);
            if (p < EQ_N) eq[p] = g_didx[j];
        }
    }
    __syncthreads();

    unsigned ngt = s_ngt; if (ngt > SRC_N) ngt = SRC_N;
    unsigned neq = s_neq; if (neq > EQ_N) neq = EQ_N;
    unsigned R = R0; if (R > neq) R = neq;

    if (neq > R) {   // rare: sort tie indices ascending, keep R smallest
        for (unsigned t = tid; t < EQ_N; t += 1024)
            if (t >= neq) eq[t] = 0xffffffffu;
        __syncthreads();
        for (unsigned k = 2; k <= EQ_N; k <<= 1) {
            for (unsigned j = k >> 1; j > 0; j >>= 1) {
                for (unsigned t = tid; t < EQ_N / 2; t += 1024) {
                    unsigned i = ((t & ~(j - 1)) << 1) | (t & (j - 1));
                    unsigned p = i | j;
                    unsigned a = eq[i], b = eq[p];
                    bool up = ((i & k) == 0);
                    if ((a > b) == up) { eq[i] = b; eq[p] = a; }
                }
                __syncthreads();
            }
        }
    }
    __syncthreads();

    for (unsigned t = tid; t < R; t += 1024)
        src[ngt + t] = ((unsigned long long)eq[t] << 32) | (unsigned long long)uT;
    unsigned total = ngt + R;                 // == KSEL in all sane runs
    if (total > SRC_N) total = SRC_N;
    __syncthreads();

    // ---- bucket sort by original index: bucket = idx >> 13 (8192 buckets)
    for (int t = tid; t < NB; t += 1024) bcnt[t] = 0;
    __syncthreads();
    for (unsigned j = tid; j < total; j += 1024)
        atomicAdd(&bcnt[(unsigned)(src[j] >> 32) >> 13], 1u);
    __syncthreads();

    // exclusive scan of bcnt[8192] (8 bins/thread, warp + block hierarchy)
    {
        unsigned v[8]; unsigned tsum = 0;
        #pragma unroll
        for (int k = 0; k < 8; k++) { unsigned c = bcnt[tid * 8 + k]; v[k] = tsum; tsum += c; }
        unsigned lane = tid & 31u, wid = tid >> 5;
        unsigned inc = tsum;
        #pragma unroll
        for (int d = 1; d < 32; d <<= 1) {
            unsigned o = __shfl_up_sync(0xffffffffu, inc, d);
            if (lane >= (unsigned)d) inc += o;
        }
        if (lane == 31) wsum[wid] = inc;
        __syncthreads();
        if (wid == 0) {
            unsigned w = wsum[lane];
            unsigned wi = w;
            #pragma unroll
            for (int d = 1; d < 32; d <<= 1) {
                unsigned o = __shfl_up_sync(0xffffffffu, wi, d);
                if (lane >= (unsigned)d) wi += o;
            }
            wsum[lane] = wi - w;   // exclusive warp base
        }
        __syncthreads();
        unsigned base = wsum[wid] + (inc - tsum);
        #pragma unroll
        for (int k = 0; k < 8; k++) bcnt[tid * 8 + k] = base + v[k];
        __syncthreads();
    }

    // scatter (post-increment turns bcnt[b] into end offsets)
    for (unsigned j = tid; j < total; j += 1024) {
        unsigned long long e = src[j];
        unsigned b = (unsigned)(e >> 32) >> 13;
        unsigned r = atomicAdd(&bcnt[b], 1u);
        if (r < SRC_N) dst[r] = e;
    }
    __syncthreads();

    // tiny per-bucket insertion sorts (bucket sizes ~0-6)
    for (unsigned b = tid; b < NB; b += 1024) {
        unsigned s0 = (b > 0) ? bcnt[b - 1] : 0;
        unsigned e0 = bcnt[b];
        if (e0 > SRC_N) e0 = SRC_N;
        for (unsigned i = s0 + 1; i < e0; i++) {
            unsigned long long key = dst[i];
            unsigned j = i;
            while (j > s0 && dst[j - 1] > key) { dst[j] = dst[j - 1]; j--; }
            dst[j] = key;
        }
    }
    __syncthreads();

    for (unsigned t = tid; t < KSEL; t += 1024)
        out[t] = u2f((unsigned)(dst[t] & 0xffffffffu));

    if (tid == 0) g_total = 0;   // restore invariant for next replay
}

// ---------------- launch ----------------------------------------------------
extern "C" void kernel_launch(void* const* d_in, const int* in_sizes, int n_in,
                              void* d_out, int out_size) {
    const float* x = (const float*)d_in[0];
    int n = in_sizes[0];
    float* out = (float*)d_out;

    cudaFuncSetAttribute(k_final, cudaFuncAttributeMaxDynamicSharedMemorySize, FIN_SMEM);

    k_compact<<<1184, 256>>>(x, n);       // 148 SMs x 8 blocks: one wave
    k_fallback<<<1, 1024>>>(x, n);        // exact slow path; ~1us early-exit
    k_final<<<1, 1024, FIN_SMEM>>>(out);
}

// round 6
// speedup vs baseline: 4.9641x; 1.0804x over previous
#include <cuda_runtime.h>

#define KSEL    5000
#define CAP     65536
#define SMEMCAP 12288
#define BUFCAP  2048
#define XGUESS  3.55f

// ---------------- scratch (static device globals; zero-initialized) ---------
__device__ unsigned int g_du[CAP];     // dense candidate keys (monotone u32)
__device__ unsigned int g_didx[CAP];   // dense candidate original indices
__device__ unsigned int g_total;       // dense candidate count (reset by k_final)
__device__ unsigned int g_ovf;         // block-buffer overflow flag

// monotone float<->uint map: larger float => larger uint
__device__ __forceinline__ unsigned int f2u(float f) {
    unsigned int b = __float_as_uint(f);
    return (b & 0x80000000u) ? ~b : (b | 0x80000000u);
}
__device__ __forceinline__ float u2f(unsigned int u) {
    return __uint_as_float((u & 0x80000000u) ? (u & 0x7fffffffu) : ~u);
}

// ---------------- K1: streaming compaction with block-local smem buffer -----
__global__ void __launch_bounds__(256) k_compact(const float* __restrict__ x, int n) {
    __shared__ unsigned s_cnt, s_base;
    __shared__ unsigned skey[BUFCAP];
    __shared__ unsigned sidx[BUFCAP];
    if (threadIdx.x == 0) s_cnt = 0;
    __syncthreads();

    const int n4 = n >> 2;
    const float4* __restrict__ x4 = (const float4*)x;
    const int stride = gridDim.x * blockDim.x;
    int i = blockIdx.x * blockDim.x + threadIdx.x;

    #define PROC4(v, base_) do {                                                  \
        float mx = fmaxf(fmaxf((v).x, (v).y), fmaxf((v).z, (v).w));               \
        unsigned am = __activemask();                                             \
        if (__ballot_sync(am, mx > XGUESS)) {                                     \
            if ((v).x > XGUESS) { unsigned p = atomicAdd(&s_cnt, 1u); if (p < BUFCAP) { skey[p] = f2u((v).x); sidx[p] = (base_) + 0; } } \
            if ((v).y > XGUESS) { unsigned p = atomicAdd(&s_cnt, 1u); if (p < BUFCAP) { skey[p] = f2u((v).y); sidx[p] = (base_) + 1; } } \
            if ((v).z > XGUESS) { unsigned p = atomicAdd(&s_cnt, 1u); if (p < BUFCAP) { skey[p] = f2u((v).z); sidx[p] = (base_) + 2; } } \
            if ((v).w > XGUESS) { unsigned p = atomicAdd(&s_cnt, 1u); if (p < BUFCAP) { skey[p] = f2u((v).w); sidx[p] = (base_) + 3; } } \
        }                                                                         \
    } while (0)

    for (; i + 3 * stride < n4; i += 4 * stride) {
        float4 a = x4[i];
        float4 b = x4[i + stride];
        float4 c = x4[i + 2 * stride];
        float4 d = x4[i + 3 * stride];
        PROC4(a, (unsigned)i << 2);
        PROC4(b, (unsigned)(i + stride) << 2);
        PROC4(c, (unsigned)(i + 2 * stride) << 2);
        PROC4(d, (unsigned)(i + 3 * stride) << 2);
    }
    for (; i < n4; i += stride) {
        float4 a = x4[i];
        PROC4(a, (unsigned)i << 2);
    }
    // scalar tail (n not divisible by 4)
    if (blockIdx.x == 0) {
        for (int t = (n4 << 2) + threadIdx.x; t < n; t += blockDim.x) {
            float v = x[t];
            if (v > XGUESS) { unsigned p = atomicAdd(&s_cnt, 1u); if (p < BUFCAP) { skey[p] = f2u(v); sidx[p] = (unsigned)t; } }
        }
    }
    __syncthreads();

    unsigned cnt = s_cnt;
    if (cnt > BUFCAP) { if (threadIdx.x == 0) g_ovf = 1u; cnt = BUFCAP; }
    if (threadIdx.x == 0) s_base = atomicAdd(&g_total, cnt);
    __syncthreads();
    unsigned base = s_base;
    for (unsigned j = threadIdx.x; j < cnt; j += blockDim.x) {
        unsigned q = base + j;
        if (q < CAP) { g_du[q] = skey[j]; g_didx[q] = sidx[j]; }
    }
}

// ---------------- K2: fused (fallback + select + gather + sort + output) ----
#define WIN_N  8192
#define NB     8192
#define EQ_N   2048
#define FIN_SMEM (SMEMCAP*8 + WIN_N*8 + NB*4 + EQ_N*4)

__global__ void __launch_bounds__(1024) k_final(const float* __restrict__ x, int n,
                                                float* __restrict__ out) {
    extern __shared__ unsigned long long sm[];
    unsigned long long* cand = sm;                     // SMEMCAP u64 (key<<32|idx)
    unsigned long long* win  = cand + SMEMCAP;         // WIN_N u64 (idx<<32|key)
    unsigned* bcnt = (unsigned*)(win + WIN_N);         // NB u32 (aliases select bins)
    unsigned* eq   = bcnt + NB;                        // EQ_N u32
    unsigned* bins = bcnt;                             // first 2048 used for select
    __shared__ unsigned sh_d, s_ngt, s_neq, wsum[32];
    const unsigned tid = threadIdx.x;

    unsigned tot = g_total;
    bool ok = (g_ovf == 0u) && tot >= (unsigned)KSEL && tot <= (unsigned)SMEMCAP;

    if (!ok) {
        // ======== exact slow fallback over full input (never runs normally) ==
        unsigned prefix = 0, prefmask = 0, need = KSEL;
        const int vsh[3] = { 21, 10, 0 };
        const int vwd[3] = { 11, 11, 10 };
        for (int r = 0; r < 3; r++) {
            const int sh = vsh[r];
            const int nb = 1 << vwd[r];
            for (int t = tid; t < nb; t += 1024) bins[t] = 0;
            __syncthreads();
            for (int i = tid; i < n; i += 1024) {
                unsigned u = f2u(x[i]);
                if ((u & prefmask) == prefix) {
                    unsigned b = (u >> sh) & (unsigned)(nb - 1);
                    unsigned am = __activemask();
                    unsigned peers = __match_any_sync(am, b);
                    if ((tid & 31u) == (unsigned)(__ffs(peers) - 1))
                        atomicAdd(&bins[b], (unsigned)__popc(peers));
                }
            }
            __syncthreads();
            for (int d = 1; d < nb; d <<= 1) {
                unsigned t0 = tid, t1 = tid + 1024;
                unsigned a0 = (t0 < (unsigned)nb && t0 + d < (unsigned)nb) ? bins[t0 + d] : 0;
                unsigned a1 = (t1 < (unsigned)nb && t1 + d < (unsigned)nb) ? bins[t1 + d] : 0;
                __syncthreads();
                if (t0 < (unsigned)nb) bins[t0] += a0;
                if (t1 < (unsigned)nb) bins[t1] += a1;
                __syncthreads();
            }
            for (int t = tid; t < nb; t += 1024) {
                unsigned nxt = (t + 1 < nb) ? bins[t + 1] : 0;
                if (bins[t] >= need && nxt < need) sh_d = (unsigned)t;
            }
            __syncthreads();
            unsigned d = sh_d;
            unsigned above = (d + 1 < (unsigned)nb) ? bins[d + 1] : 0;
            __syncthreads();
            need -= above;
            prefix |= d << sh;
            prefmask |= ((unsigned)(nb - 1)) << sh;
        }
        const unsigned uT = prefix;
        const unsigned R = need;

        unsigned iprefix = 0, imask = 0, needi = R;
        const int ish[3] = { 15, 4, 0 };
        const int iwd[3] = { 11, 11, 4 };
        if (R > 0) {
            for (int r = 0; r < 3; r++) {
                const int sh = ish[r];
                const int nb = 1 << iwd[r];
                for (int t = tid; t < nb; t += 1024) bins[t] = 0;
                __syncthreads();
                for (int i = tid; i < n; i += 1024) {
                    unsigned u = f2u(x[i]);
                    if (u == uT && (((unsigned)i & imask) == iprefix))
                        atomicAdd(&bins[((unsigned)i >> sh) & (unsigned)(nb - 1)], 1u);
                }
                __syncthreads();
                for (int d = 1; d < nb; d <<= 1) {
                    unsigned t0 = tid, t1 = tid + 1024;
                    unsigned a0 = (t0 < (unsigned)nb && t0 >= (unsigned)d) ? bins[t0 - d] : 0;
                    unsigned a1 = (t1 < (unsigned)nb && t1 >= (unsigned)d) ? bins[t1 - d] : 0;
                    __syncthreads();
                    if (t0 < (unsigned)nb) bins[t0] += a0;
                    if (t1 < (unsigned)nb) bins[t1] += a1;
                    __syncthreads();
                }
                for (int t = tid; t < nb; t += 1024) {
                    unsigned prev = (t > 0) ? bins[t - 1] : 0;
                    if (bins[t] >= needi && prev < needi) sh_d = (unsigned)t;
                }
                __syncthreads();
                unsigned d = sh_d;
                unsigned below = (d > 0) ? bins[d - 1] : 0;
                __syncthreads();
                needi -= below;
                iprefix |= d << sh;
                imask |= ((unsigned)(nb - 1)) << sh;
            }
        }
        if (tid == 0) g_total = 0;
        __syncthreads();
        for (int i = tid; i < n; i += 1024) {
            unsigned u = f2u(x[i]);
            bool keep = (u > uT) || (R > 0 && u == uT && (unsigned)i <= iprefix);
            if (keep) {
                unsigned p = atomicAdd(&g_total, 1u);
                if (p < CAP) { g_du[p] = u; g_didx[p] = (unsigned)i; }
            }
        }
        __syncthreads();
        tot = g_total;                         // == KSEL <= SMEMCAP
        if (tot > (unsigned)SMEMCAP) tot = SMEMCAP;
    }

    const unsigned T = tot;

    // ---- stage candidates into smem (high MLP bulk copy)
    for (unsigned j = tid; j < T; j += 1024) {
        unsigned u = g_du[j];
        unsigned ix = g_didx[j];
        cand[j] = ((unsigned long long)u << 32) | (unsigned long long)ix;
    }
    __syncthreads();

    // ---- exact radix select over smem candidates (3 rounds: 11/11/10 bits)
    unsigned prefix = 0, prefmask = 0, need = KSEL;
    const int shifts[3] = { 21, 10, 0 };
    const int widths[3] = { 11, 11, 10 };
    for (int r = 0; r < 3; r++) {
        const int sh = shifts[r];
        const int nb = 1 << widths[r];
        for (int t = tid; t < nb; t += 1024) bins[t] = 0;
        __syncthreads();

        for (unsigned base = 0; base < T; base += 1024) {
            unsigned j = base + tid;
            bool valid = (j < T);
            unsigned u = valid ? (unsigned)(cand[j] >> 32) : 0u;
            bool act = valid && ((u & prefmask) == prefix);
            unsigned b = (u >> sh) & (unsigned)(nb - 1);
            unsigned m = __ballot_sync(0xffffffffu, act);
            if (act) {
                unsigned peers = __match_any_sync(m, b);
                if ((tid & 31u) == (unsigned)(__ffs(peers) - 1))
                    atomicAdd(&bins[b], (unsigned)__popc(peers));
            }
        }
        __syncthreads();

        for (int d = 1; d < nb; d <<= 1) {
            unsigned tmp[2]; int c = 0;
            for (int t = tid; t < nb; t += 1024)
                tmp[c++] = (t + d < nb) ? bins[t + d] : 0;
            __syncthreads();
            c = 0;
            for (int t = tid; t < nb; t += 1024)
                bins[t] += tmp[c++];
            __syncthreads();
        }
        for (int t = tid; t < nb; t += 1024) {
            unsigned nxt = (t + 1 < nb) ? bins[t + 1] : 0;
            if (bins[t] >= need && nxt < need) sh_d = (unsigned)t;
        }
        __syncthreads();
        unsigned d = sh_d;
        unsigned above = (d + 1 < (unsigned)nb) ? bins[d + 1] : 0;
        __syncthreads();
        need -= above;
        prefix |= d << sh;
        prefmask |= ((unsigned)(nb - 1)) << sh;
    }
    const unsigned uT = prefix;
    const unsigned R0 = need;

    // ---- gather winners (> uT) and tie indices (== uT), all from smem
    if (tid == 0) { s_ngt = 0; s_neq = 0; }
    __syncthreads();
    for (unsigned j = tid; j < T; j += 1024) {
        unsigned long long e = cand[j];
        unsigned u = (unsigned)(e >> 32);
        unsigned ix = (unsigned)e;
        if (u > uT) {
            unsigned p = atomicAdd(&s_ngt, 1u);
            if (p < WIN_N) win[p] = ((unsigned long long)ix << 32) | (unsigned long long)u;
        } else if (u == uT) {
            unsigned p = atomicAdd(&s_neq, 1u);
            if (p < EQ_N) eq[p] = ix;
        }
    }
    __syncthreads();

    unsigned ngt = s_ngt; if (ngt > WIN_N) ngt = WIN_N;
    unsigned neq = s_neq; if (neq > EQ_N) neq = EQ_N;
    unsigned R = R0; if (R > neq) R = neq;

    if (neq > R) {   // rare: sort tie indices ascending, keep R smallest
        for (unsigned t = tid; t < EQ_N; t += 1024)
            if (t >= neq) eq[t] = 0xffffffffu;
        __syncthreads();
        for (unsigned k = 2; k <= EQ_N; k <<= 1) {
            for (unsigned j = k >> 1; j > 0; j >>= 1) {
                for (unsigned t = tid; t < EQ_N / 2; t += 1024) {
                    unsigned i2 = ((t & ~(j - 1)) << 1) | (t & (j - 1));
                    unsigned p2 = i2 | j;
                    unsigned a = eq[i2], b = eq[p2];
                    bool up = ((i2 & k) == 0);
                    if ((a > b) == up) { eq[i2] = b; eq[p2] = a; }
                }
                __syncthreads();
            }
        }
    }
    __syncthreads();

    for (unsigned t = tid; t < R; t += 1024)
        win[ngt + t] = ((unsigned long long)eq[t] << 32) | (unsigned long long)uT;
    unsigned total = ngt + R;                 // == KSEL in all sane runs
    if (total > WIN_N) total = WIN_N;
    __syncthreads();

    // ---- bucket sort winners by original index: bucket = idx >> 13
    for (int t = tid; t < NB; t += 1024) bcnt[t] = 0;
    __syncthreads();
    for (unsigned j = tid; j < total; j += 1024)
        atomicAdd(&bcnt[(unsigned)(win[j] >> 32) >> 13], 1u);
    __syncthreads();

    {   // exclusive scan of bcnt[NB] (8 bins/thread, warp+block hierarchy)
        unsigned v[8]; unsigned tsum = 0;
        #pragma unroll
        for (int k = 0; k < 8; k++) { unsigned c = bcnt[tid * 8 + k]; v[k] = tsum; tsum += c; }
        unsigned lane = tid & 31u, wid = tid >> 5;
        unsigned inc = tsum;
        #pragma unroll
        for (int d = 1; d < 32; d <<= 1) {
            unsigned o = __shfl_up_sync(0xffffffffu, inc, d);
            if (lane >= (unsigned)d) inc += o;
        }
        if (lane == 31) wsum[wid] = inc;
        __syncthreads();
        if (wid == 0) {
            unsigned w = wsum[lane];
            unsigned wi = w;
            #pragma unroll
            for (int d = 1; d < 32; d <<= 1) {
                unsigned o = __shfl_up_sync(0xffffffffu, wi, d);
                if (lane >= (unsigned)d) wi += o;
            }
            wsum[lane] = wi - w;
        }
        __syncthreads();
        unsigned base = wsum[wid] + (inc - tsum);
        #pragma unroll
        for (int k = 0; k < 8; k++) bcnt[tid * 8 + k] = base + v[k];
        __syncthreads();
    }

    // scatter into cand[] (reuse as output buffer; post-increment -> end offsets)
    for (unsigned j = tid; j < total; j += 1024) {
        unsigned long long e = win[j];
        unsigned b = (unsigned)(e >> 32) >> 13;
        unsigned r = atomicAdd(&bcnt[b], 1u);
        if (r < SMEMCAP) cand[r] = e;
    }
    __syncthreads();

    // tiny per-bucket insertion sorts (bucket sizes ~0-6)
    for (unsigned b = tid; b < NB; b += 1024) {
        unsigned s0 = (b > 0) ? bcnt[b - 1] : 0;
        unsigned e0 = bcnt[b];
        if (e0 > SMEMCAP) e0 = SMEMCAP;
        for (unsigned i2 = s0 + 1; i2 < e0; i2++) {
            unsigned long long key = cand[i2];
            unsigned j2 = i2;
            while (j2 > s0 && cand[j2 - 1] > key) { cand[j2] = cand[j2 - 1]; j2--; }
            cand[j2] = key;
        }
    }
    __syncthreads();

    for (unsigned t = tid; t < KSEL; t += 1024)
        out[t] = u2f((unsigned)(cand[t] & 0xffffffffu));

    if (tid == 0) { g_total = 0; g_ovf = 0; }   // restore invariant for replay
}

// ---------------- launch ----------------------------------------------------
extern "C" void kernel_launch(void* const* d_in, const int* in_sizes, int n_in,
                              void* d_out, int out_size) {
    const float* x = (const float*)d_in[0];
    int n = in_sizes[0];
    float* out = (float*)d_out;

    cudaFuncSetAttribute(k_final, cudaFuncAttributeMaxDynamicSharedMemorySize, FIN_SMEM);

    k_compact<<<1184, 256>>>(x, n);            // 148 SMs x 8 blocks: one wave
    k_final<<<1, 1024, FIN_SMEM>>>(x, n, out); // fallback check + select + sort
}

// round 7
// speedup vs baseline: 6.9418x; 1.3984x over previous
#include <cuda_runtime.h>

#define KSEL    5000
#define CAP     65536
#define SMEMCAP 12288
#define BUFCAP  2048
#define XGUESS  3.55f
#define NHIST   4096

// ---------------- scratch (static device globals; zero-initialized) ---------
__device__ unsigned int g_du[CAP];     // dense candidate keys (monotone u32)
__device__ unsigned int g_didx[CAP];   // dense candidate original indices
__device__ unsigned int g_hist[NHIST]; // coarse histogram of (key-UB)>>13
__device__ unsigned int g_total;       // dense candidate count (reset by k_final)
__device__ unsigned int g_ovf;         // block-buffer overflow flag

// monotone float<->uint map: larger float => larger uint
__device__ __forceinline__ unsigned int f2u(float f) {
    unsigned int b = __float_as_uint(f);
    return (b & 0x80000000u) ? ~b : (b | 0x80000000u);
}
__device__ __forceinline__ float u2f(unsigned int u) {
    return __uint_as_float((u & 0x80000000u) ? (u & 0x7fffffffu) : ~u);
}

// ---------------- K1: streaming compaction + coarse histogram ---------------
__global__ void __launch_bounds__(512) k_compact(const float* __restrict__ x, int n) {
    __shared__ unsigned s_cnt, s_base;
    __shared__ unsigned skey[BUFCAP];
    __shared__ unsigned sidx[BUFCAP];
    if (threadIdx.x == 0) s_cnt = 0;
    __syncthreads();

    const int n4 = n >> 2;
    const float4* __restrict__ x4 = (const float4*)x;
    const int stride = gridDim.x * blockDim.x;
    int i = blockIdx.x * blockDim.x + threadIdx.x;

    #define PROC4(v, base_) do {                                                  \
        float mx = fmaxf(fmaxf((v).x, (v).y), fmaxf((v).z, (v).w));               \
        unsigned am = __activemask();                                             \
        if (__ballot_sync(am, mx > XGUESS)) {                                     \
            if ((v).x > XGUESS) { unsigned p = atomicAdd(&s_cnt, 1u); if (p < BUFCAP) { skey[p] = f2u((v).x); sidx[p] = (base_) + 0; } } \
            if ((v).y > XGUESS) { unsigned p = atomicAdd(&s_cnt, 1u); if (p < BUFCAP) { skey[p] = f2u((v).y); sidx[p] = (base_) + 1; } } \
            if ((v).z > XGUESS) { unsigned p = atomicAdd(&s_cnt, 1u); if (p < BUFCAP) { skey[p] = f2u((v).z); sidx[p] = (base_) + 2; } } \
            if ((v).w > XGUESS) { unsigned p = atomicAdd(&s_cnt, 1u); if (p < BUFCAP) { skey[p] = f2u((v).w); sidx[p] = (base_) + 3; } } \
        }                                                                         \
    } while (0)

    for (; i + 3 * stride < n4; i += 4 * stride) {
        float4 a = __ldcs(x4 + i);
        float4 b = __ldcs(x4 + i + stride);
        float4 c = __ldcs(x4 + i + 2 * stride);
        float4 d = __ldcs(x4 + i + 3 * stride);
        PROC4(a, (unsigned)i << 2);
        PROC4(b, (unsigned)(i + stride) << 2);
        PROC4(c, (unsigned)(i + 2 * stride) << 2);
        PROC4(d, (unsigned)(i + 3 * stride) << 2);
    }
    for (; i < n4; i += stride) {
        float4 a = __ldcs(x4 + i);
        PROC4(a, (unsigned)i << 2);
    }
    // scalar tail (n not divisible by 4)
    if (blockIdx.x == 0) {
        for (int t = (n4 << 2) + threadIdx.x; t < n; t += blockDim.x) {
            float v = x[t];
            if (v > XGUESS) { unsigned p = atomicAdd(&s_cnt, 1u); if (p < BUFCAP) { skey[p] = f2u(v); sidx[p] = (unsigned)t; } }
        }
    }
    __syncthreads();

    unsigned cnt = s_cnt;
    if (cnt > BUFCAP) { if (threadIdx.x == 0) g_ovf = 1u; cnt = BUFCAP; }
    if (threadIdx.x == 0) s_base = atomicAdd(&g_total, cnt);
    __syncthreads();
    const unsigned UB = f2u(XGUESS);
    unsigned base = s_base;
    for (unsigned j = threadIdx.x; j < cnt; j += blockDim.x) {
        unsigned q = base + j;
        unsigned key = skey[j];
        if (q < CAP) { g_du[q] = key; g_didx[q] = sidx[j]; }
        unsigned b = (key - UB) >> 13; if (b > NHIST - 1u) b = NHIST - 1u;
        atomicAdd(&g_hist[b], 1u);
    }
}

// ---------------- hierarchical inclusive SUFFIX scan over smem bins ---------
template <int NB_>
__device__ __forceinline__ void suffix_scan_block(unsigned* b, unsigned* wsum) {
    constexpr int NPT = NB_ / 1024;
    const unsigned tid = threadIdx.x;
    const unsigned lane = tid & 31u, wid = tid >> 5;
    unsigned v[NPT]; unsigned tsum = 0;
    const unsigned base = tid * NPT;
    #pragma unroll
    for (int k = 0; k < NPT; k++) { v[k] = b[base + k]; tsum += v[k]; }
    // warp-level inclusive suffix of tsum
    unsigned inc = tsum;
    #pragma unroll
    for (int d = 1; d < 32; d <<= 1) {
        unsigned o = __shfl_down_sync(0xffffffffu, inc, d);
        if (lane + d < 32) inc += o;
    }
    if (lane == 0) wsum[wid] = inc;          // warp total
    __syncthreads();
    if (wid == 0) {
        unsigned w = wsum[lane];
        unsigned wi = w;
        #pragma unroll
        for (int d = 1; d < 32; d <<= 1) {
            unsigned o = __shfl_down_sync(0xffffffffu, wi, d);
            if (lane + d < 32) wi += o;
        }
        wsum[lane] = wi - w;                 // sum of warps AFTER this warp
    }
    __syncthreads();
    unsigned acc = wsum[wid] + (inc - tsum); // sum of all bins after this chunk
    #pragma unroll
    for (int k = NPT - 1; k >= 0; k--) { acc += v[k]; b[base + k] = acc; }
    __syncthreads();
}

// ---------------- K2: fused (select + gather + sort + output + fallback) ----
#define WIN_N  8192
#define NB     8192
#define EQ_N   2048
#define FIN_SMEM (SMEMCAP*8 + WIN_N*8 + NB*4 + EQ_N*4)

__global__ void __launch_bounds__(1024) k_final(const float* __restrict__ x, int n,
                                                float* __restrict__ out) {
    extern __shared__ unsigned long long sm[];
    unsigned long long* cand = sm;                     // SMEMCAP u64 (key<<32|idx)
    unsigned long long* win  = cand + SMEMCAP;         // WIN_N u64 (idx<<32|key)
    unsigned* bcnt = (unsigned*)(win + WIN_N);         // NB u32 (select bins / buckets)
    unsigned* eq   = bcnt + NB;                        // EQ_N u32
    unsigned* bins = bcnt;
    __shared__ unsigned sh_d, sh_ab, s_ngt, s_neq, wsum[32];
    const unsigned tid = threadIdx.x;
    const unsigned UB = f2u(XGUESS);

    unsigned tot = g_total;
    bool ok = (g_ovf == 0u) && tot >= (unsigned)KSEL && tot <= (unsigned)SMEMCAP;

    unsigned T = 0, uT = 0, R0 = 0;
    bool have = false;

    if (ok) {
        T = tot;
        // stage candidates into smem (high-MLP bulk copy)
        for (unsigned j = tid; j < T; j += 1024)
            cand[j] = ((unsigned long long)g_du[j] << 32) | (unsigned long long)g_didx[j];
        // load coarse histogram
        for (unsigned t = tid; t < NHIST; t += 1024) bcnt[t] = g_hist[t];
        __syncthreads();

        suffix_scan_block<NHIST>(bcnt, wsum);
        for (unsigned t = tid; t < NHIST; t += 1024) {
            unsigned nxt = (t + 1 < NHIST) ? bcnt[t + 1] : 0;
            if (bcnt[t] >= (unsigned)KSEL && nxt < (unsigned)KSEL) { sh_d = t; sh_ab = nxt; }
        }
        __syncthreads();
        unsigned d = sh_d, aboveBin = sh_ab;
        __syncthreads();

        if (d < NHIST - 1u) {
            unsigned need2 = (unsigned)KSEL - aboveBin;   // >= 1
            // fine histogram: 1-key-wide bins within coarse bin d
            for (unsigned t = tid; t < NB; t += 1024) bcnt[t] = 0;
            __syncthreads();
            for (unsigned j = tid; j < T; j += 1024) {
                unsigned u = (unsigned)(cand[j] >> 32);
                unsigned del = u - UB;
                if ((del >> 13) == d) atomicAdd(&bcnt[del & 8191u], 1u);
            }
            __syncthreads();
            suffix_scan_block<NB>(bcnt, wsum);
            for (unsigned t = tid; t < NB; t += 1024) {
                unsigned nxt = (t + 1 < NB) ? bcnt[t + 1] : 0;
                if (bcnt[t] >= need2 && nxt < need2) { sh_d = t; sh_ab = nxt; }
            }
            __syncthreads();
            unsigned o = sh_d, aboveKey = sh_ab;
            uT = UB + (d << 13) + o;                      // exact threshold key
            R0 = need2 - aboveKey;                        // ties to keep
            have = true;
            __syncthreads();
        }
    }

    if (!have) {
        // ======== exact slow fallback over full input (never runs normally) ==
        unsigned prefix = 0, prefmask = 0, need = KSEL;
        const int vsh[3] = { 21, 10, 0 };
        const int vwd[3] = { 11, 11, 10 };
        for (int r = 0; r < 3; r++) {
            const int sh = vsh[r];
            const int nb = 1 << vwd[r];
            for (int t = tid; t < nb; t += 1024) bins[t] = 0;
            __syncthreads();
            for (int i = tid; i < n; i += 1024) {
                unsigned u = f2u(x[i]);
                if ((u & prefmask) == prefix) {
                    unsigned b = (u >> sh) & (unsigned)(nb - 1);
                    unsigned am = __activemask();
                    unsigned peers = __match_any_sync(am, b);
                    if ((tid & 31u) == (unsigned)(__ffs(peers) - 1))
                        atomicAdd(&bins[b], (unsigned)__popc(peers));
                }
            }
            __syncthreads();
            for (int d2 = 1; d2 < nb; d2 <<= 1) {
                unsigned t0 = tid, t1 = tid + 1024;
                unsigned a0 = (t0 < (unsigned)nb && t0 + d2 < (unsigned)nb) ? bins[t0 + d2] : 0;
                unsigned a1 = (t1 < (unsigned)nb && t1 + d2 < (unsigned)nb) ? bins[t1 + d2] : 0;
                __syncthreads();
                if (t0 < (unsigned)nb) bins[t0] += a0;
                if (t1 < (unsigned)nb) bins[t1] += a1;
                __syncthreads();
            }
            for (int t = tid; t < nb; t += 1024) {
                unsigned nxt = (t + 1 < nb) ? bins[t + 1] : 0;
                if (bins[t] >= need && nxt < need) sh_d = (unsigned)t;
            }
            __syncthreads();
            unsigned d2 = sh_d;
            unsigned above = (d2 + 1 < (unsigned)nb) ? bins[d2 + 1] : 0;
            __syncthreads();
            need -= above;
            prefix |= d2 << sh;
            prefmask |= ((unsigned)(nb - 1)) << sh;
        }
        const unsigned uTf = prefix;
        const unsigned Rf = need;

        unsigned iprefix = 0, imask = 0, needi = Rf;
        const int ish[3] = { 15, 4, 0 };
        const int iwd[3] = { 11, 11, 4 };
        if (Rf > 0) {
            for (int r = 0; r < 3; r++) {
                const int sh = ish[r];
                const int nb = 1 << iwd[r];
                for (int t = tid; t < nb; t += 1024) bins[t] = 0;
                __syncthreads();
                for (int i = tid; i < n; i += 1024) {
                    unsigned u = f2u(x[i]);
                    if (u == uTf && (((unsigned)i & imask) == iprefix))
                        atomicAdd(&bins[((unsigned)i >> sh) & (unsigned)(nb - 1)], 1u);
                }
                __syncthreads();
                for (int d2 = 1; d2 < nb; d2 <<= 1) {
                    unsigned t0 = tid, t1 = tid + 1024;
                    unsigned a0 = (t0 < (unsigned)nb && t0 >= (unsigned)d2) ? bins[t0 - d2] : 0;
                    unsigned a1 = (t1 < (unsigned)nb && t1 >= (unsigned)d2) ? bins[t1 - d2] : 0;
                    __syncthreads();
                    if (t0 < (unsigned)nb) bins[t0] += a0;
                    if (t1 < (unsigned)nb) bins[t1] += a1;
                    __syncthreads();
                }
                for (int t = tid; t < nb; t += 1024) {
                    unsigned prev = (t > 0) ? bins[t - 1] : 0;
                    if (bins[t] >= needi && prev < needi) sh_d = (unsigned)t;
                }
                __syncthreads();
                unsigned d2 = sh_d;
                unsigned below = (d2 > 0) ? bins[d2 - 1] : 0;
                __syncthreads();
                needi -= below;
                iprefix |= d2 << sh;
                imask |= ((unsigned)(nb - 1)) << sh;
            }
        }
        if (tid == 0) g_total = 0;
        __syncthreads();
        for (int i = tid; i < n; i += 1024) {
            unsigned u = f2u(x[i]);
            bool keep = (u > uTf) || (Rf > 0 && u == uTf && (unsigned)i <= iprefix);
            if (keep) {
                unsigned p = atomicAdd(&g_total, 1u);
                if (p < CAP) { g_du[p] = u; g_didx[p] = (unsigned)i; }
            }
        }
        __syncthreads();
        T = g_total; if (T > (unsigned)SMEMCAP) T = SMEMCAP;
        for (unsigned j = tid; j < T; j += 1024)
            cand[j] = ((unsigned long long)g_du[j] << 32) | (unsigned long long)g_didx[j];
        uT = 0; R0 = 0;          // every staged candidate is a winner (u > 0)
        __syncthreads();
    }

    // ---- gather winners (> uT) and tie indices (== uT), all from smem
    if (tid == 0) { s_ngt = 0; s_neq = 0; }
    __syncthreads();
    for (unsigned j = tid; j < T; j += 1024) {
        unsigned long long e = cand[j];
        unsigned u = (unsigned)(e >> 32);
        unsigned ix = (unsigned)e;
        if (u > uT) {
            unsigned p = atomicAdd(&s_ngt, 1u);
            if (p < WIN_N) win[p] = ((unsigned long long)ix << 32) | (unsigned long long)u;
        } else if (u == uT) {
            unsigned p = atomicAdd(&s_neq, 1u);
            if (p < EQ_N) eq[p] = ix;
        }
    }
    __syncthreads();

    unsigned ngt = s_ngt; if (ngt > WIN_N) ngt = WIN_N;
    unsigned neq = s_neq; if (neq > EQ_N) neq = EQ_N;
    unsigned R = R0; if (R > neq) R = neq;

    if (neq > R) {   // rare: sort tie indices ascending, keep R smallest
        for (unsigned t = tid; t < EQ_N; t += 1024)
            if (t >= neq) eq[t] = 0xffffffffu;
        __syncthreads();
        for (unsigned k = 2; k <= EQ_N; k <<= 1) {
            for (unsigned j = k >> 1; j > 0; j >>= 1) {
                for (unsigned t = tid; t < EQ_N / 2; t += 1024) {
                    unsigned i2 = ((t & ~(j - 1)) << 1) | (t & (j - 1));
                    unsigned p2 = i2 | j;
                    unsigned a = eq[i2], b = eq[p2];
                    bool up = ((i2 & k) == 0);
                    if ((a > b) == up) { eq[i2] = b; eq[p2] = a; }
                }
                __syncthreads();
            }
        }
    }
    __syncthreads();

    for (unsigned t = tid; t < R; t += 1024)
        win[ngt + t] = ((unsigned long long)eq[t] << 32) | (unsigned long long)uT;
    unsigned total = ngt + R;                 // == KSEL in all sane runs
    if (total > WIN_N) total = WIN_N;
    __syncthreads();

    // ---- bucket sort winners by original index: bucket = idx >> 13
    for (unsigned t = tid; t < NB; t += 1024) bcnt[t] = 0;
    __syncthreads();
    for (unsigned j = tid; j < total; j += 1024)
        atomicAdd(&bcnt[(unsigned)(win[j] >> 32) >> 13], 1u);
    __syncthreads();

    {   // exclusive scan of bcnt[NB] (8 bins/thread, warp+block hierarchy)
        unsigned v[8]; unsigned tsum = 0;
        #pragma unroll
        for (int k = 0; k < 8; k++) { unsigned c = bcnt[tid * 8 + k]; v[k] = tsum; tsum += c; }
        unsigned lane = tid & 31u, wid2 = tid >> 5;
        unsigned inc = tsum;
        #pragma unroll
        for (int d = 1; d < 32; d <<= 1) {
            unsigned o = __shfl_up_sync(0xffffffffu, inc, d);
            if (lane >= (unsigned)d) inc += o;
        }
        if (lane == 31) wsum[wid2] = inc;
        __syncthreads();
        if (wid2 == 0) {
            unsigned w = wsum[lane];
            unsigned wi = w;
            #pragma unroll
            for (int d = 1; d < 32; d <<= 1) {
                unsigned o = __shfl_up_sync(0xffffffffu, wi, d);
                if (lane >= (unsigned)d) wi += o;
            }
            wsum[lane] = wi - w;
        }
        __syncthreads();
        unsigned base = wsum[wid2] + (inc - tsum);
        #pragma unroll
        for (int k = 0; k < 8; k++) bcnt[tid * 8 + k] = base + v[k];
        __syncthreads();
    }

    // scatter into cand[] (reuse as output buffer; post-increment -> end offsets)
    for (unsigned j = tid; j < total; j += 1024) {
        unsigned long long e = win[j];
        unsigned b = (unsigned)(e >> 32) >> 13;
        unsigned r = atomicAdd(&bcnt[b], 1u);
        if (r < SMEMCAP) cand[r] = e;
    }
    __syncthreads();

    // tiny per-bucket insertion sorts (bucket sizes ~0-6)
    for (unsigned b = tid; b < NB; b += 1024) {
        unsigned s0 = (b > 0) ? bcnt[b - 1] : 0;
        unsigned e0 = bcnt[b];
        if (e0 > SMEMCAP) e0 = SMEMCAP;
        for (unsigned i2 = s0 + 1; i2 < e0; i2++) {
            unsigned long long key = cand[i2];
            unsigned j2 = i2;
            while (j2 > s0 && cand[j2 - 1] > key) { cand[j2] = cand[j2 - 1]; j2--; }
            cand[j2] = key;
        }
    }
    __syncthreads();

    for (unsigned t = tid; t < KSEL; t += 1024)
        out[t] = u2f((unsigned)(cand[t] & 0xffffffffu));

    // restore invariants for next graph replay
    for (unsigned t = tid; t < NHIST; t += 1024) g_hist[t] = 0;
    if (tid == 0) { g_total = 0; g_ovf = 0; }
}

// ---------------- launch ----------------------------------------------------
extern "C" void kernel_launch(void* const* d_in, const int* in_sizes, int n_in,
                              void* d_out, int out_size) {
    const float* x = (const float*)d_in[0];
    int n = in_sizes[0];
    float* out = (float*)d_out;

    cudaFuncSetAttribute(k_final, cudaFuncAttributeMaxDynamicSharedMemorySize, FIN_SMEM);

    k_compact<<<592, 512>>>(x, n);             // 148 SMs x 4 blocks: one wave
    k_final<<<1, 1024, FIN_SMEM>>>(x, n, out); // select + gather + sort + out
}

// round 8
// speedup vs baseline: 7.2436x; 1.0435x over previous
#include <cuda_runtime.h>

#define KSEL    5000
#define CAP     65536
#define SMEMCAP 12288
#define BUFCAP  2048
#define XGUESS  3.55f
#define NHIST   4096
#define NB      8192
#define EQ_N    2048
#define DST_N   5120

// ---------------- scratch (static device globals; zero-initialized) ---------
__device__ unsigned int g_du[CAP];     // dense candidate keys (monotone u32)
__device__ unsigned int g_didx[CAP];   // dense candidate original indices
__device__ unsigned int g_hist[NHIST]; // coarse histogram of (key-UB)>>13
__device__ unsigned int g_total;       // dense candidate count (reset by k_final)
__device__ unsigned int g_ovf;         // block-buffer overflow flag

// monotone float<->uint map: larger float => larger uint
__device__ __forceinline__ unsigned int f2u(float f) {
    unsigned int b = __float_as_uint(f);
    return (b & 0x80000000u) ? ~b : (b | 0x80000000u);
}
__device__ __forceinline__ float u2f(unsigned int u) {
    return __uint_as_float((u & 0x80000000u) ? (u & 0x7fffffffu) : ~u);
}

// ---------------- K1: streaming compaction + coarse histogram ---------------
__global__ void __launch_bounds__(512) k_compact(const float* __restrict__ x, int n) {
    __shared__ unsigned s_cnt, s_base;
    __shared__ unsigned skey[BUFCAP];
    __shared__ unsigned sidx[BUFCAP];
    if (threadIdx.x == 0) s_cnt = 0;
    __syncthreads();

    const int n4 = n >> 2;
    const float4* __restrict__ x4 = (const float4*)x;
    const int stride = gridDim.x * blockDim.x;
    int i = blockIdx.x * blockDim.x + threadIdx.x;

    #define PROC4(v, base_) do {                                                  \
        float mx = fmaxf(fmaxf((v).x, (v).y), fmaxf((v).z, (v).w));               \
        unsigned am = __activemask();                                             \
        if (__ballot_sync(am, mx > XGUESS)) {                                     \
            if ((v).x > XGUESS) { unsigned p = atomicAdd(&s_cnt, 1u); if (p < BUFCAP) { skey[p] = f2u((v).x); sidx[p] = (base_) + 0; } } \
            if ((v).y > XGUESS) { unsigned p = atomicAdd(&s_cnt, 1u); if (p < BUFCAP) { skey[p] = f2u((v).y); sidx[p] = (base_) + 1; } } \
            if ((v).z > XGUESS) { unsigned p = atomicAdd(&s_cnt, 1u); if (p < BUFCAP) { skey[p] = f2u((v).z); sidx[p] = (base_) + 2; } } \
            if ((v).w > XGUESS) { unsigned p = atomicAdd(&s_cnt, 1u); if (p < BUFCAP) { skey[p] = f2u((v).w); sidx[p] = (base_) + 3; } } \
        }                                                                         \
    } while (0)

    for (; i + 3 * stride < n4; i += 4 * stride) {
        float4 a = __ldcs(x4 + i);
        float4 b = __ldcs(x4 + i + stride);
        float4 c = __ldcs(x4 + i + 2 * stride);
        float4 d = __ldcs(x4 + i + 3 * stride);
        PROC4(a, (unsigned)i << 2);
        PROC4(b, (unsigned)(i + stride) << 2);
        PROC4(c, (unsigned)(i + 2 * stride) << 2);
        PROC4(d, (unsigned)(i + 3 * stride) << 2);
    }
    for (; i < n4; i += stride) {
        float4 a = __ldcs(x4 + i);
        PROC4(a, (unsigned)i << 2);
    }
    if (blockIdx.x == 0) {       // scalar tail (n not divisible by 4)
        for (int t = (n4 << 2) + threadIdx.x; t < n; t += blockDim.x) {
            float v = x[t];
            if (v > XGUESS) { unsigned p = atomicAdd(&s_cnt, 1u); if (p < BUFCAP) { skey[p] = f2u(v); sidx[p] = (unsigned)t; } }
        }
    }
    __syncthreads();

    unsigned cnt = s_cnt;
    if (cnt > BUFCAP) { if (threadIdx.x == 0) g_ovf = 1u; cnt = BUFCAP; }
    if (threadIdx.x == 0) s_base = atomicAdd(&g_total, cnt);
    __syncthreads();
    const unsigned UB = f2u(XGUESS);
    unsigned base = s_base;
    for (unsigned j = threadIdx.x; j < cnt; j += blockDim.x) {
        unsigned q = base + j;
        unsigned key = skey[j];
        if (q < CAP) { g_du[q] = key; g_didx[q] = sidx[j]; }
        unsigned b = (key - UB) >> 13; if (b > NHIST - 1u) b = NHIST - 1u;
        atomicAdd(&g_hist[b], 1u);
    }
}

// ---------------- hierarchical inclusive SUFFIX scan over smem bins ---------
template <int NBINS>
__device__ __forceinline__ void suffix_scan_block(unsigned* b, unsigned* wsum) {
    constexpr int NPT = NBINS / 1024;
    const unsigned tid = threadIdx.x;
    const unsigned lane = tid & 31u, wid = tid >> 5;
    unsigned v[NPT]; unsigned tsum = 0;
    const unsigned base = tid * NPT;
    #pragma unroll
    for (int k = 0; k < NPT; k++) { v[k] = b[base + k]; tsum += v[k]; }
    unsigned inc = tsum;
    #pragma unroll
    for (int d = 1; d < 32; d <<= 1) {
        unsigned o = __shfl_down_sync(0xffffffffu, inc, d);
        if (lane + d < 32) inc += o;
    }
    if (lane == 0) wsum[wid] = inc;
    __syncthreads();
    if (wid == 0) {
        unsigned w = wsum[lane];
        unsigned wi = w;
        #pragma unroll
        for (int d = 1; d < 32; d <<= 1) {
            unsigned o = __shfl_down_sync(0xffffffffu, wi, d);
            if (lane + d < 32) wi += o;
        }
        wsum[lane] = wi - w;                 // sum of warps after this warp
    }
    __syncthreads();
    unsigned acc = wsum[wid] + (inc - tsum);
    #pragma unroll
    for (int k = NPT - 1; k >= 0; k--) { acc += v[k]; b[base + k] = acc; }
    __syncthreads();
}

// ---------------- K2: fused select + bucket sort + output (+ fallback) ------
#define FIN_SMEM (SMEMCAP*8 + DST_N*8 + NB*4 + EQ_N*4)

__global__ void __launch_bounds__(1024) k_final(const float* __restrict__ x, int n,
                                                float* __restrict__ out) {
    extern __shared__ unsigned long long sm[];
    unsigned long long* cand = sm;                  // SMEMCAP u64 (key<<32|idx)
    unsigned long long* dst  = cand + SMEMCAP;      // DST_N u64 (idx<<32|key)
    unsigned* bcnt = (unsigned*)(dst + DST_N);      // NB u32 (hist/scan/buckets)
    unsigned* eq   = bcnt + NB;                     // EQ_N u32
    unsigned* bins = bcnt;
    __shared__ unsigned sh_d, sh_ab, s_neq, wsum[32];
    const unsigned tid = threadIdx.x;
    const unsigned UB = f2u(XGUESS);

    unsigned tot = g_total;
    bool ok = (g_ovf == 0u) && tot >= (unsigned)KSEL && tot <= (unsigned)SMEMCAP;

    unsigned T = 0, uT = 0, R0 = 0;
    bool have = false;

    if (ok) {
        T = tot;
        // coarse suffix scan over g_hist (no candidate data needed yet)
        for (unsigned t = tid; t < NHIST; t += 1024) bcnt[t] = g_hist[t];
        __syncthreads();
        suffix_scan_block<NHIST>(bcnt, wsum);
        for (unsigned t = tid; t < NHIST; t += 1024) {
            unsigned nxt = (t + 1 < NHIST) ? bcnt[t + 1] : 0;
            if (bcnt[t] >= (unsigned)KSEL && nxt < (unsigned)KSEL) { sh_d = t; sh_ab = nxt; }
        }
        __syncthreads();
        unsigned d = sh_d, aboveBin = sh_ab;
        __syncthreads();

        if (d < NHIST - 1u) {
            unsigned need2 = (unsigned)KSEL - aboveBin;   // >= 1
            for (unsigned t = tid; t < NB; t += 1024) bcnt[t] = 0;
            __syncthreads();
            // fused: stage candidates into smem + fine histogram of bin d
            for (unsigned base = 0; base < T; base += 1024) {
                unsigned j = base + tid;
                if (j < T) {
                    unsigned u = g_du[j], ix = g_didx[j];
                    cand[j] = ((unsigned long long)u << 32) | (unsigned long long)ix;
                    unsigned del = u - UB;
                    if ((del >> 13) == d) atomicAdd(&bcnt[del & (NB - 1u)], 1u);
                }
            }
            __syncthreads();
            suffix_scan_block<NB>(bcnt, wsum);
            for (unsigned t = tid; t < NB; t += 1024) {
                unsigned nxt = (t + 1 < NB) ? bcnt[t + 1] : 0;
                if (bcnt[t] >= need2 && nxt < need2) { sh_d = t; sh_ab = nxt; }
            }
            __syncthreads();
            unsigned o = sh_d, aboveKey = sh_ab;
            uT = UB + (d << 13) + o;                      // exact threshold key
            R0 = need2 - aboveKey;                        // ties to keep
            have = true;
            __syncthreads();
        }
    }

    if (!have) {
        // ======== exact slow fallback over full input (never runs normally) ==
        unsigned prefix = 0, prefmask = 0, need = KSEL;
        const int vsh[3] = { 21, 10, 0 };
        const int vwd[3] = { 11, 11, 10 };
        for (int r = 0; r < 3; r++) {
            const int sh = vsh[r];
            const int nb = 1 << vwd[r];
            for (int t = tid; t < nb; t += 1024) bins[t] = 0;
            __syncthreads();
            for (int i = tid; i < n; i += 1024) {
                unsigned u = f2u(x[i]);
                if ((u & prefmask) == prefix) {
                    unsigned b = (u >> sh) & (unsigned)(nb - 1);
                    unsigned am = __activemask();
                    unsigned peers = __match_any_sync(am, b);
                    if ((tid & 31u) == (unsigned)(__ffs(peers) - 1))
                        atomicAdd(&bins[b], (unsigned)__popc(peers));
                }
            }
            __syncthreads();
            for (int d2 = 1; d2 < nb; d2 <<= 1) {
                unsigned t0 = tid, t1 = tid + 1024;
                unsigned a0 = (t0 < (unsigned)nb && t0 + d2 < (unsigned)nb) ? bins[t0 + d2] : 0;
                unsigned a1 = (t1 < (unsigned)nb && t1 + d2 < (unsigned)nb) ? bins[t1 + d2] : 0;
                __syncthreads();
                if (t0 < (unsigned)nb) bins[t0] += a0;
                if (t1 < (unsigned)nb) bins[t1] += a1;
                __syncthreads();
            }
            for (int t = tid; t < nb; t += 1024) {
                unsigned nxt = (t + 1 < nb) ? bins[t + 1] : 0;
                if (bins[t] >= need && nxt < need) sh_d = (unsigned)t;
            }
            __syncthreads();
            unsigned d2 = sh_d;
            unsigned above = (d2 + 1 < (unsigned)nb) ? bins[d2 + 1] : 0;
            __syncthreads();
            need -= above;
            prefix |= d2 << sh;
            prefmask |= ((unsigned)(nb - 1)) << sh;
        }
        const unsigned uTf = prefix;
        const unsigned Rf = need;

        unsigned iprefix = 0, imask = 0, needi = Rf;
        const int ish[3] = { 15, 4, 0 };
        const int iwd[3] = { 11, 11, 4 };
        if (Rf > 0) {
            for (int r = 0; r < 3; r++) {
                const int sh = ish[r];
                const int nb = 1 << iwd[r];
                for (int t = tid; t < nb; t += 1024) bins[t] = 0;
                __syncthreads();
                for (int i = tid; i < n; i += 1024) {
                    unsigned u = f2u(x[i]);
                    if (u == uTf && (((unsigned)i & imask) == iprefix))
                        atomicAdd(&bins[((unsigned)i >> sh) & (unsigned)(nb - 1)], 1u);
                }
                __syncthreads();
                for (int d2 = 1; d2 < nb; d2 <<= 1) {
                    unsigned t0 = tid, t1 = tid + 1024;
                    unsigned a0 = (t0 < (unsigned)nb && t0 >= (unsigned)d2) ? bins[t0 - d2] : 0;
                    unsigned a1 = (t1 < (unsigned)nb && t1 >= (unsigned)d2) ? bins[t1 - d2] : 0;
                    __syncthreads();
                    if (t0 < (unsigned)nb) bins[t0] += a0;
                    if (t1 < (unsigned)nb) bins[t1] += a1;
                    __syncthreads();
                }
                for (int t = tid; t < nb; t += 1024) {
                    unsigned prev = (t > 0) ? bins[t - 1] : 0;
                    if (bins[t] >= needi && prev < needi) sh_d = (unsigned)t;
                }
                __syncthreads();
                unsigned d2 = sh_d;
                unsigned below = (d2 > 0) ? bins[d2 - 1] : 0;
                __syncthreads();
                needi -= below;
                iprefix |= d2 << sh;
                imask |= ((unsigned)(nb - 1)) << sh;
            }
        }
        if (tid == 0) g_total = 0;
        __syncthreads();
        for (int i = tid; i < n; i += 1024) {
            unsigned u = f2u(x[i]);
            bool keep = (u > uTf) || (Rf > 0 && u == uTf && (unsigned)i <= iprefix);
            if (keep) {
                unsigned p = atomicAdd(&g_total, 1u);
                if (p < CAP) { g_du[p] = u; g_didx[p] = (unsigned)i; }
            }
        }
        __syncthreads();
        T = g_total; if (T > (unsigned)SMEMCAP) T = SMEMCAP;
        for (unsigned j = tid; j < T; j += 1024)
            cand[j] = ((unsigned long long)g_du[j] << 32) | (unsigned long long)g_didx[j];
        uT = 0; R0 = 0;          // every staged candidate is a winner (u > 0)
        __syncthreads();
    }

    // ---- tie-cut: collect indices of keys == uT (warp-aggregated, tiny set)
    if (tid == 0) s_neq = 0;
    __syncthreads();
    if (R0 > 0) {
        for (unsigned base = 0; base < T; base += 1024) {
            unsigned j = base + tid;
            bool pred = false; unsigned ix = 0;
            if (j < T) {
                unsigned long long e = cand[j];
                pred = ((unsigned)(e >> 32) == uT);
                ix = (unsigned)e;
            }
            unsigned mask = __ballot_sync(0xffffffffu, pred);
            if (mask) {
                unsigned lane = tid & 31u;
                unsigned leader = (unsigned)(__ffs(mask) - 1);
                unsigned wbase = 0;
                if (lane == leader) wbase = atomicAdd(&s_neq, (unsigned)__popc(mask));
                wbase = __shfl_sync(0xffffffffu, wbase, leader);
                if (pred) {
                    unsigned pos = wbase + (unsigned)__popc(mask & ((1u << lane) - 1u));
                    if (pos < EQ_N) eq[pos] = ix;
                }
            }
        }
    }
    __syncthreads();

    unsigned neq = s_neq; if (neq > EQ_N) neq = EQ_N;
    unsigned R = R0; if (R > neq) R = neq;
    unsigned cut = 0xffffffffu;              // keep all ties when neq == R
    if (R > 0 && neq > R) {
        // minimal-size bitonic sort of eq[0..np2), ascending
        unsigned np2 = 2; while (np2 < neq) np2 <<= 1;
        for (unsigned t = tid; t < np2; t += 1024)
            if (t >= neq) eq[t] = 0xffffffffu;
        __syncthreads();
        for (unsigned k = 2; k <= np2; k <<= 1) {
            for (unsigned j = k >> 1; j > 0; j >>= 1) {
                for (unsigned t = tid; t < np2 / 2; t += 1024) {
                    unsigned i2 = ((t & ~(j - 1)) << 1) | (t & (j - 1));
                    unsigned p2 = i2 | j;
                    unsigned a = eq[i2], b = eq[p2];
                    bool up = ((i2 & k) == 0);
                    if ((a > b) == up) { eq[i2] = b; eq[p2] = a; }
                }
                __syncthreads();
            }
        }
        cut = eq[R - 1];
    }
    __syncthreads();

    // ---- bucket sort straight from cand[]: bucket = idx >> 13
    for (unsigned t = tid; t < NB; t += 1024) bcnt[t] = 0;
    __syncthreads();
    for (unsigned base = 0; base < T; base += 1024) {
        unsigned j = base + tid;
        if (j < T) {
            unsigned long long e = cand[j];
            unsigned u = (unsigned)(e >> 32), ix = (unsigned)e;
            bool keep = (u > uT) || (R > 0 && u == uT && ix <= cut);
            if (keep) atomicAdd(&bcnt[ix >> 13], 1u);
        }
    }
    __syncthreads();

    {   // exclusive scan of bcnt[NB] (8 bins/thread, warp+block hierarchy)
        unsigned v[8]; unsigned tsum = 0;
        #pragma unroll
        for (int k = 0; k < 8; k++) { unsigned c = bcnt[tid * 8 + k]; v[k] = tsum; tsum += c; }
        unsigned lane = tid & 31u, wid2 = tid >> 5;
        unsigned inc = tsum;
        #pragma unroll
        for (int d = 1; d < 32; d <<= 1) {
            unsigned o = __shfl_up_sync(0xffffffffu, inc, d);
            if (lane >= (unsigned)d) inc += o;
        }
        if (lane == 31) wsum[wid2] = inc;
        __syncthreads();
        if (wid2 == 0) {
            unsigned w = wsum[lane];
            unsigned wi = w;
            #pragma unroll
            for (int d = 1; d < 32; d <<= 1) {
                unsigned o = __shfl_up_sync(0xffffffffu, wi, d);
                if (lane >= (unsigned)d) wi += o;
            }
            wsum[lane] = wi - w;
        }
        __syncthreads();
        unsigned base = wsum[wid2] + (inc - tsum);
        #pragma unroll
        for (int k = 0; k < 8; k++) bcnt[tid * 8 + k] = base + v[k];
        __syncthreads();
    }

    // scatter keepers into dst (post-increment turns bcnt into end offsets)
    for (unsigned base = 0; base < T; base += 1024) {
        unsigned j = base + tid;
        if (j < T) {
            unsigned long long e = cand[j];
            unsigned u = (unsigned)(e >> 32), ix = (unsigned)e;
            bool keep = (u > uT) || (R > 0 && u == uT && ix <= cut);
            if (keep) {
                unsigned r = atomicAdd(&bcnt[ix >> 13], 1u);
                if (r < DST_N) dst[r] = ((unsigned long long)ix << 32) | (unsigned long long)u;
            }
        }
    }
    __syncthreads();

    // tiny per-bucket insertion sorts (bucket sizes ~0-6)
    for (unsigned b = tid; b < NB; b += 1024) {
        unsigned s0 = (b > 0) ? bcnt[b - 1] : 0;
        unsigned e0 = bcnt[b];
        if (s0 > DST_N) s0 = DST_N;
        if (e0 > DST_N) e0 = DST_N;
        for (unsigned i2 = s0 + 1; i2 < e0; i2++) {
            unsigned long long key = dst[i2];
            unsigned j2 = i2;
            while (j2 > s0 && dst[j2 - 1] > key) { dst[j2] = dst[j2 - 1]; j2--; }
            dst[j2] = key;
        }
    }
    __syncthreads();

    for (unsigned t = tid; t < KSEL; t += 1024)
        out[t] = u2f((unsigned)(dst[t] & 0xffffffffu));

    // restore invariants for next graph replay
    for (unsigned t = tid; t < NHIST; t += 1024) g_hist[t] = 0;
    if (tid == 0) { g_total = 0; g_ovf = 0; }
}

// ---------------- launch ----------------------------------------------------
extern "C" void kernel_launch(void* const* d_in, const int* in_sizes, int n_in,
                              void* d_out, int out_size) {
    const float* x = (const float*)d_in[0];
    int n = in_sizes[0];
    float* out = (float*)d_out;

    cudaFuncSetAttribute(k_final, cudaFuncAttributeMaxDynamicSharedMemorySize, FIN_SMEM);

    k_compact<<<592, 512>>>(x, n);             // 148 SMs x 4 blocks: one wave
    k_final<<<1, 1024, FIN_SMEM>>>(x, n, out); // select + bucket sort + output
}

// round 9
// speedup vs baseline: 7.6251x; 1.0527x over previous
#include <cuda_runtime.h>

#define KSEL     5000
#define CAP      65536
#define SMEMCAP  12288
#define NPT_CAND 12          // SMEMCAP / 1024
#define BUFCAP   2048
#define XGUESS   3.55f
#define NHIST    4096
#define NB       8192
#define EQ_N     2048
#define DST_N    5120

// ---------------- scratch (static device globals; zero-initialized) ---------
__device__ unsigned int g_du[CAP];     // dense candidate keys (monotone u32)
__device__ unsigned int g_didx[CAP];   // dense candidate original indices
__device__ unsigned int g_hist[NHIST]; // coarse histogram of (key-UB)>>13
__device__ unsigned int g_total;       // dense candidate count
__device__ unsigned int g_ovf;         // block-buffer overflow flag
__device__ unsigned int g_mode;        // 1 => fallback ran; g_du holds winners

// monotone float<->uint map: larger float => larger uint
__device__ __forceinline__ unsigned int f2u(float f) {
    unsigned int b = __float_as_uint(f);
    return (b & 0x80000000u) ? ~b : (b | 0x80000000u);
}
__device__ __forceinline__ float u2f(unsigned int u) {
    return __uint_as_float((u & 0x80000000u) ? (u & 0x7fffffffu) : ~u);
}

// ---------------- K1: streaming compaction + coarse histogram ---------------
__global__ void __launch_bounds__(512) k_compact(const float* __restrict__ x, int n) {
    __shared__ unsigned s_cnt, s_base;
    __shared__ unsigned skey[BUFCAP];
    __shared__ unsigned sidx[BUFCAP];
    if (threadIdx.x == 0) s_cnt = 0;
    __syncthreads();

    const int n4 = n >> 2;
    const float4* __restrict__ x4 = (const float4*)x;
    const int stride = gridDim.x * blockDim.x;
    int i = blockIdx.x * blockDim.x + threadIdx.x;

    #define PROC4(v, base_) do {                                                  \
        float mx = fmaxf(fmaxf((v).x, (v).y), fmaxf((v).z, (v).w));               \
        unsigned am = __activemask();                                             \
        if (__ballot_sync(am, mx > XGUESS)) {                                     \
            if ((v).x > XGUESS) { unsigned p = atomicAdd(&s_cnt, 1u); if (p < BUFCAP) { skey[p] = f2u((v).x); sidx[p] = (base_) + 0; } } \
            if ((v).y > XGUESS) { unsigned p = atomicAdd(&s_cnt, 1u); if (p < BUFCAP) { skey[p] = f2u((v).y); sidx[p] = (base_) + 1; } } \
            if ((v).z > XGUESS) { unsigned p = atomicAdd(&s_cnt, 1u); if (p < BUFCAP) { skey[p] = f2u((v).z); sidx[p] = (base_) + 2; } } \
            if ((v).w > XGUESS) { unsigned p = atomicAdd(&s_cnt, 1u); if (p < BUFCAP) { skey[p] = f2u((v).w); sidx[p] = (base_) + 3; } } \
        }                                                                         \
    } while (0)

    for (; i + 3 * stride < n4; i += 4 * stride) {
        float4 a = __ldcs(x4 + i);
        float4 b = __ldcs(x4 + i + stride);
        float4 c = __ldcs(x4 + i + 2 * stride);
        float4 d = __ldcs(x4 + i + 3 * stride);
        PROC4(a, (unsigned)i << 2);
        PROC4(b, (unsigned)(i + stride) << 2);
        PROC4(c, (unsigned)(i + 2 * stride) << 2);
        PROC4(d, (unsigned)(i + 3 * stride) << 2);
    }
    for (; i < n4; i += stride) {
        float4 a = __ldcs(x4 + i);
        PROC4(a, (unsigned)i << 2);
    }
    if (blockIdx.x == 0) {       // scalar tail (n not divisible by 4)
        for (int t = (n4 << 2) + threadIdx.x; t < n; t += blockDim.x) {
            float v = x[t];
            if (v > XGUESS) { unsigned p = atomicAdd(&s_cnt, 1u); if (p < BUFCAP) { skey[p] = f2u(v); sidx[p] = (unsigned)t; } }
        }
    }
    __syncthreads();

    unsigned cnt = s_cnt;
    if (cnt > BUFCAP) { if (threadIdx.x == 0) g_ovf = 1u; cnt = BUFCAP; }
    if (threadIdx.x == 0) s_base = atomicAdd(&g_total, cnt);
    __syncthreads();
    const unsigned UB = f2u(XGUESS);
    unsigned base = s_base;
    for (unsigned j = threadIdx.x; j < cnt; j += blockDim.x) {
        unsigned q = base + j;
        unsigned key = skey[j];
        if (q < CAP) { g_du[q] = key; g_didx[q] = sidx[j]; }
        unsigned b = (key - UB) >> 13; if (b > NHIST - 1u) b = NHIST - 1u;
        atomicAdd(&g_hist[b], 1u);
    }
}

// ---------------- K2: exact full-input fallback (separate small kernel) -----
__global__ void __launch_bounds__(1024) k_fallback(const float* __restrict__ x, int n) {
    {
        unsigned tot = g_total;
        bool ok = (g_ovf == 0u) && tot >= (unsigned)KSEL && tot <= (unsigned)SMEMCAP
                  && (g_hist[NHIST - 1] < (unsigned)KSEL);
        if (ok) return;
    }
    __shared__ unsigned bins[2048];
    __shared__ unsigned sh_d;
    const unsigned tid = threadIdx.x;

    // exact value threshold: 3-level radix (11/11/10 bits), descending
    unsigned prefix = 0, prefmask = 0, need = KSEL;
    const int vsh[3] = { 21, 10, 0 };
    const int vwd[3] = { 11, 11, 10 };
    for (int r = 0; r < 3; r++) {
        const int sh = vsh[r];
        const int nb = 1 << vwd[r];
        for (int t = tid; t < nb; t += 1024) bins[t] = 0;
        __syncthreads();
        for (int i = tid; i < n; i += 1024) {
            unsigned u = f2u(x[i]);
            if ((u & prefmask) == prefix) {
                unsigned b = (u >> sh) & (unsigned)(nb - 1);
                unsigned am = __activemask();
                unsigned peers = __match_any_sync(am, b);
                if ((tid & 31u) == (unsigned)(__ffs(peers) - 1))
                    atomicAdd(&bins[b], (unsigned)__popc(peers));
            }
        }
        __syncthreads();
        for (int d2 = 1; d2 < nb; d2 <<= 1) {
            unsigned t0 = tid, t1 = tid + 1024;
            unsigned a0 = (t0 < (unsigned)nb && t0 + d2 < (unsigned)nb) ? bins[t0 + d2] : 0;
            unsigned a1 = (t1 < (unsigned)nb && t1 + d2 < (unsigned)nb) ? bins[t1 + d2] : 0;
            __syncthreads();
            if (t0 < (unsigned)nb) bins[t0] += a0;
            if (t1 < (unsigned)nb) bins[t1] += a1;
            __syncthreads();
        }
        for (int t = tid; t < nb; t += 1024) {
            unsigned nxt = (t + 1 < nb) ? bins[t + 1] : 0;
            if (bins[t] >= need && nxt < need) sh_d = (unsigned)t;
        }
        __syncthreads();
        unsigned d2 = sh_d;
        unsigned above = (d2 + 1 < (unsigned)nb) ? bins[d2 + 1] : 0;
        __syncthreads();
        need -= above;
        prefix |= d2 << sh;
        prefmask |= ((unsigned)(nb - 1)) << sh;
    }
    const unsigned uTf = prefix;
    const unsigned Rf = need;

    // exact tie-index threshold: 3-level radix (11/11/4 bits), ascending
    unsigned iprefix = 0, imask = 0, needi = Rf;
    const int ish[3] = { 15, 4, 0 };
    const int iwd[3] = { 11, 11, 4 };
    if (Rf > 0) {
        for (int r = 0; r < 3; r++) {
            const int sh = ish[r];
            const int nb = 1 << iwd[r];
            for (int t = tid; t < nb; t += 1024) bins[t] = 0;
            __syncthreads();
            for (int i = tid; i < n; i += 1024) {
                unsigned u = f2u(x[i]);
                if (u == uTf && (((unsigned)i & imask) == iprefix))
                    atomicAdd(&bins[((unsigned)i >> sh) & (unsigned)(nb - 1)], 1u);
            }
            __syncthreads();
            for (int d2 = 1; d2 < nb; d2 <<= 1) {
                unsigned t0 = tid, t1 = tid + 1024;
                unsigned a0 = (t0 < (unsigned)nb && t0 >= (unsigned)d2) ? bins[t0 - d2] : 0;
                unsigned a1 = (t1 < (unsigned)nb && t1 >= (unsigned)d2) ? bins[t1 - d2] : 0;
                __syncthreads();
                if (t0 < (unsigned)nb) bins[t0] += a0;
                if (t1 < (unsigned)nb) bins[t1] += a1;
                __syncthreads();
            }
            for (int t = tid; t < nb; t += 1024) {
                unsigned prev = (t > 0) ? bins[t - 1] : 0;
                if (bins[t] >= needi && prev < needi) sh_d = (unsigned)t;
            }
            __syncthreads();
            unsigned d2 = sh_d;
            unsigned below = (d2 > 0) ? bins[d2 - 1] : 0;
            __syncthreads();
            needi -= below;
            iprefix |= d2 << sh;
            imask |= ((unsigned)(nb - 1)) << sh;
        }
    }
    if (tid == 0) g_total = 0;
    __syncthreads();
    for (int i = tid; i < n; i += 1024) {
        unsigned u = f2u(x[i]);
        bool keep = (u > uTf) || (Rf > 0 && u == uTf && (unsigned)i <= iprefix);
        if (keep) {
            unsigned p = atomicAdd(&g_total, 1u);
            if (p < CAP) { g_du[p] = u; g_didx[p] = (unsigned)i; }
        }
    }
    if (tid == 0) g_mode = 1u;   // g_du now holds exactly the winners
}

// ---------------- vectorized hierarchical suffix scan (inclusive) -----------
template <int NBINS>
__device__ __forceinline__ void suffix_scan_block(unsigned* b, unsigned* wsum) {
    constexpr int NPT = NBINS / 1024;     // 4 or 8
    constexpr int NV = NPT / 4;
    const unsigned tid = threadIdx.x;
    const unsigned lane = tid & 31u, wid = tid >> 5;
    uint4* b4 = (uint4*)b;
    unsigned v[NPT]; unsigned tsum = 0;
    #pragma unroll
    for (int q = 0; q < NV; q++) {
        uint4 t4 = b4[tid * NV + q];
        v[q*4+0] = t4.x; v[q*4+1] = t4.y; v[q*4+2] = t4.z; v[q*4+3] = t4.w;
    }
    #pragma unroll
    for (int k = 0; k < NPT; k++) tsum += v[k];
    unsigned inc = tsum;
    #pragma unroll
    for (int d = 1; d < 32; d <<= 1) {
        unsigned o = __shfl_down_sync(0xffffffffu, inc, d);
        if (lane + d < 32) inc += o;
    }
    if (lane == 0) wsum[wid] = inc;
    __syncthreads();
    if (wid == 0) {
        unsigned w = wsum[lane];
        unsigned wi = w;
        #pragma unroll
        for (int d = 1; d < 32; d <<= 1) {
            unsigned o = __shfl_down_sync(0xffffffffu, wi, d);
            if (lane + d < 32) wi += o;
        }
        wsum[lane] = wi - w;                 // sum of warps after this warp
    }
    __syncthreads();
    unsigned acc = wsum[wid] + (inc - tsum);
    #pragma unroll
    for (int k = NPT - 1; k >= 0; k--) { acc += v[k]; v[k] = acc; }
    #pragma unroll
    for (int q = 0; q < NV; q++)
        b4[tid * NV + q] = make_uint4(v[q*4+0], v[q*4+1], v[q*4+2], v[q*4+3]);
    __syncthreads();
}

// vectorized hierarchical EXCLUSIVE scan over 8192 bins
__device__ __forceinline__ void excl_scan_8192(unsigned* b, unsigned* wsum) {
    const unsigned tid = threadIdx.x;
    const unsigned lane = tid & 31u, wid2 = tid >> 5;
    uint4* b4 = (uint4*)b;
    uint4 a0 = b4[tid * 2], a1 = b4[tid * 2 + 1];
    unsigned v[8] = { a0.x, a0.y, a0.z, a0.w, a1.x, a1.y, a1.z, a1.w };
    unsigned pre[8]; unsigned tsum = 0;
    #pragma unroll
    for (int k = 0; k < 8; k++) { pre[k] = tsum; tsum += v[k]; }
    unsigned inc = tsum;
    #pragma unroll
    for (int d = 1; d < 32; d <<= 1) {
        unsigned o = __shfl_up_sync(0xffffffffu, inc, d);
        if (lane >= (unsigned)d) inc += o;
    }
    if (lane == 31) wsum[wid2] = inc;
    __syncthreads();
    if (wid2 == 0) {
        unsigned w = wsum[lane];
        unsigned wi = w;
        #pragma unroll
        for (int d = 1; d < 32; d <<= 1) {
            unsigned o = __shfl_up_sync(0xffffffffu, wi, d);
            if (lane >= (unsigned)d) wi += o;
        }
        wsum[lane] = wi - w;
    }
    __syncthreads();
    unsigned base = wsum[wid2] + (inc - tsum);
    b4[tid * 2]     = make_uint4(base + pre[0], base + pre[1], base + pre[2], base + pre[3]);
    b4[tid * 2 + 1] = make_uint4(base + pre[4], base + pre[5], base + pre[6], base + pre[7]);
    __syncthreads();
}

// ---------------- K3: select + bucket sort + output (register-resident) -----
#define FIN_SMEM (DST_N*8 + NB*4 + EQ_N*4)

__global__ void __launch_bounds__(1024) k_final(float* __restrict__ out) {
    extern __shared__ unsigned long long sm[];
    unsigned long long* dst = sm;                   // DST_N u64 (idx<<32|key)
    unsigned* bcnt = (unsigned*)(dst + DST_N);      // NB u32 (hist/scan/buckets)
    unsigned* eq   = bcnt + NB;                     // EQ_N u32
    __shared__ unsigned sh_d, sh_ab, s_neq, wsum[32];
    const unsigned tid = threadIdx.x;
    const unsigned UB = f2u(XGUESS);

    const unsigned mode = g_mode;
    unsigned T = g_total; if (T > (unsigned)SMEMCAP) T = SMEMCAP;

    // load candidates into registers immediately (latency hidden by coarse scan)
    unsigned uk[NPT_CAND], ui[NPT_CAND];
    #pragma unroll
    for (int k = 0; k < NPT_CAND; k++) {
        unsigned j = tid + (unsigned)k * 1024u;
        bool vld = (j < T);
        uk[k] = vld ? g_du[j] : 0u;     // key 0 is never kept / never a tie
        ui[k] = vld ? g_didx[j] : 0u;
    }

    unsigned uT = 0, R0 = 0;
    if (mode == 0u) {
        // coarse suffix scan over g_hist
        for (unsigned t = tid; t < NHIST; t += 1024) bcnt[t] = g_hist[t];
        __syncthreads();
        suffix_scan_block<NHIST>(bcnt, wsum);
        for (unsigned t = tid; t < NHIST; t += 1024) {
            unsigned nxt = (t + 1 < NHIST) ? bcnt[t + 1] : 0;
            if (bcnt[t] >= (unsigned)KSEL && nxt < (unsigned)KSEL) { sh_d = t; sh_ab = nxt; }
        }
        __syncthreads();
        const unsigned d = sh_d, aboveBin = sh_ab;      // d < NHIST-1 guaranteed
        const unsigned need2 = (unsigned)KSEL - aboveBin;
        __syncthreads();

        // fine histogram (1-key-wide bins) from registers
        for (unsigned t = tid; t < NB; t += 1024) bcnt[t] = 0;
        __syncthreads();
        #pragma unroll
        for (int k = 0; k < NPT_CAND; k++) {
            unsigned del = uk[k] - UB;
            if ((del >> 13) == d) atomicAdd(&bcnt[del & (NB - 1u)], 1u);
        }
        __syncthreads();
        suffix_scan_block<NB>(bcnt, wsum);
        for (unsigned t = tid; t < NB; t += 1024) {
            unsigned nxt = (t + 1 < NB) ? bcnt[t + 1] : 0;
            if (bcnt[t] >= need2 && nxt < need2) { sh_d = t; sh_ab = nxt; }
        }
        __syncthreads();
        uT = UB + (d << 13) + sh_d;                     // exact threshold key
        R0 = need2 - sh_ab;                             // ties to keep
        __syncthreads();
    }
    // mode 1: uT=0, R0=0 — every staged candidate (key>0) is a winner.

    // ---- tie-cut: collect indices of keys == uT (warp-aggregated, tiny set)
    if (tid == 0) s_neq = 0;
    __syncthreads();
    if (R0 > 0) {
        #pragma unroll
        for (int k = 0; k < NPT_CAND; k++) {
            bool pred = (uk[k] == uT);
            unsigned mask = __ballot_sync(0xffffffffu, pred);
            if (mask) {
                unsigned lane = tid & 31u;
                unsigned leader = (unsigned)(__ffs(mask) - 1);
                unsigned wbase = 0;
                if (lane == leader) wbase = atomicAdd(&s_neq, (unsigned)__popc(mask));
                wbase = __shfl_sync(0xffffffffu, wbase, leader);
                if (pred) {
                    unsigned pos = wbase + (unsigned)__popc(mask & ((1u << lane) - 1u));
                    if (pos < EQ_N) eq[pos] = ui[k];
                }
            }
        }
    }
    __syncthreads();

    unsigned neq = s_neq; if (neq > EQ_N) neq = EQ_N;
    unsigned R = R0; if (R > neq) R = neq;
    unsigned cut = 0xffffffffu;              // keep all ties when neq == R
    if (R > 0 && neq > R) {
        unsigned np2 = 2; while (np2 < neq) np2 <<= 1;
        for (unsigned t = tid; t < np2; t += 1024)
            if (t >= neq) eq[t] = 0xffffffffu;
        __syncthreads();
        for (unsigned k = 2; k <= np2; k <<= 1) {
            for (unsigned j = k >> 1; j > 0; j >>= 1) {
                for (unsigned t = tid; t < np2 / 2; t += 1024) {
                    unsigned i2 = ((t & ~(j - 1)) << 1) | (t & (j - 1));
                    unsigned p2 = i2 | j;
                    unsigned a = eq[i2], b = eq[p2];
                    bool up = ((i2 & k) == 0);
                    if ((a > b) == up) { eq[i2] = b; eq[p2] = a; }
                }
                __syncthreads();
            }
        }
        cut = eq[R - 1];
        __syncthreads();
    }

    // ---- bucket sort from registers: bucket = idx >> 13
    for (unsigned t = tid; t < NB; t += 1024) bcnt[t] = 0;
    __syncthreads();
    #pragma unroll
    for (int k = 0; k < NPT_CAND; k++) {
        unsigned u = uk[k];
        bool keep = (u > uT) || (R > 0 && u == uT && ui[k] <= cut);
        if (keep) atomicAdd(&bcnt[ui[k] >> 13], 1u);
    }
    __syncthreads();

    excl_scan_8192(bcnt, wsum);

    // scatter keepers into dst (post-increment turns bcnt into end offsets)
    #pragma unroll
    for (int k = 0; k < NPT_CAND; k++) {
        unsigned u = uk[k], ix = ui[k];
        bool keep = (u > uT) || (R > 0 && u == uT && ix <= cut);
        if (keep) {
            unsigned r = atomicAdd(&bcnt[ix >> 13], 1u);
            if (r < DST_N) dst[r] = ((unsigned long long)ix << 32) | (unsigned long long)u;
        }
    }
    __syncthreads();

    // tiny per-bucket insertion sorts (bucket sizes ~0-6)
    for (unsigned b = tid; b < NB; b += 1024) {
        unsigned s0 = (b > 0) ? bcnt[b - 1] : 0;
        unsigned e0 = bcnt[b];
        if (s0 > (unsigned)DST_N) s0 = DST_N;
        if (e0 > (unsigned)DST_N) e0 = DST_N;
        for (unsigned i2 = s0 + 1; i2 < e0; i2++) {
            unsigned long long key = dst[i2];
            unsigned j2 = i2;
            while (j2 > s0 && dst[j2 - 1] > key) { dst[j2] = dst[j2 - 1]; j2--; }
            dst[j2] = key;
        }
    }
    __syncthreads();

    for (unsigned t = tid; t < KSEL; t += 1024)
        out[t] = u2f((unsigned)(dst[t] & 0xffffffffu));

    // restore invariants for next graph replay
    for (unsigned t = tid; t < NHIST; t += 1024) g_hist[t] = 0;
    if (tid == 0) { g_total = 0; g_ovf = 0; g_mode = 0; }
}

// ---------------- launch ----------------------------------------------------
extern "C" void kernel_launch(void* const* d_in, const int* in_sizes, int n_in,
                              void* d_out, int out_size) {
    const float* x = (const float*)d_in[0];
    int n = in_sizes[0];
    float* out = (float*)d_out;

    cudaFuncSetAttribute(k_final, cudaFuncAttributeMaxDynamicSharedMemorySize, FIN_SMEM);

    k_compact<<<592, 512>>>(x, n);        // 148 SMs x 4 blocks: one wave
    k_fallback<<<1, 1024>>>(x, n);        // exact slow path; early-exit normally
    k_final<<<1, 1024, FIN_SMEM>>>(out);  // select + bucket sort + output
}